// round 12
// baseline (speedup 1.0000x reference)
#include <cuda_runtime.h>
#include <cuda_bf16.h>
#include <math.h>
#include <string.h>

// ---------------------------------------------------------------------------
// Problem constants
// ---------------------------------------------------------------------------
#define BATCH 4
#define IMG_H 512
#define IMG_W 1408
#define FH 64
#define FW 176
#define NPIX (FH*FW)            // 11264
#define HM_SZ (BATCH*NPIX)      // 45056
#define BEV 512
#define BEV_SZ (BATCH*BEV*BEV)  // 1048576
#define TOPK 200
#define THR 0.15f
#define EPSV 1e-4f

#define OFF_HM     0
#define OFF_DEPTH  (HM_SZ)
#define OFF_LOGITS (2*HM_SZ)
#define OFF_PROB   (2*HM_SZ + BEV_SZ)

// Padded geometry (1-px halo, width padded to mult of 4)
#define PW1 708
#define PH1 258
#define PLANE1 (PH1*PW1)        // x1: 32 ch, 256x704
#define PW2 356
#define PH2 130
#define PLANE2 (PH2*PW2)        // x2: 64 ch, 128x352
#define PW3 180
#define PH3 66
#define PLANE3 (PH3*PW3)        // feats/h1/d1: 96 ch, 64x176

// ---------------------------------------------------------------------------
// Scratch (device globals: zero-initialized at module load; halos never
// written by any kernel, so they remain zero across all graph replays)
// ---------------------------------------------------------------------------
__device__ float g_x1[BATCH*32*PLANE1 + 4096];
__device__ float g_x2[BATCH*64*PLANE2 + 4096];
__device__ float g_feats[BATCH*96*PLANE3 + 4096];
__device__ float g_h1[BATCH*96*PLANE3 + 4096];
__device__ float g_d1[BATCH*96*PLANE3 + 4096];

// ---------------------------------------------------------------------------
// f32x2 packed math helpers
// ---------------------------------------------------------------------------
__device__ __forceinline__ unsigned long long pack2(float x) {
    unsigned long long r;
    const unsigned int u = __float_as_uint(x);
    asm("mov.b64 %0, {%1, %1};" : "=l"(r) : "r"(u));
    return r;
}
#define FMA2(acc, a, b) \
    asm("fma.rn.f32x2 %0, %1, %2, %0;" : "+l"(acc) : "l"(a), "l"(b))

// ---------------------------------------------------------------------------
// Padded direct 3x3 conv + BN(eval) + ReLU using packed f32x2 FMAs (R7 core).
// Used for conv2 and conv3 (proven configs).
// ---------------------------------------------------------------------------
template<int IC, int OC, int OCPT, int STRIDE, int PXC>
__global__ void __launch_bounds__(128, 4)
convp(const float* __restrict__ in, int PWI, int planeI,
      int OH, int OW, int PWO, int planeO,
      const float* __restrict__ w0, const float* __restrict__ ga0,
      const float* __restrict__ be0, float* __restrict__ out0)
{
    constexpr int NG  = OC / OCPT;
    constexpr int NOP = OCPT / 2;
    constexpr int NF4 = NOP / 2;
    constexpr int NIN = (PXC - 1) * STRIDE + 3;
    constexpr int NV2 = (NIN + 1) / 2;

    int z = blockIdx.z;
    const int g = z % NG;
    const int b = z / NG;

    const float* wgt   = w0;
    const float* gamma = ga0;
    const float* beta  = be0;
    float*       out   = out0;

    const int l  = threadIdx.x;
    const int oy = blockIdx.y * 4 + threadIdx.y;
    const int x0 = (blockIdx.x * 32 + l) * PXC;

    __shared__ __align__(16) float ws[IC * 9 * OCPT];
    {
        const int tid = threadIdx.y * 32 + l;
        const float* wsrc = wgt + (size_t)(g * OCPT) * IC * 9;
        for (int i = tid; i < IC * 9 * OCPT; i += 128) {
            const int ocl = i % OCPT;
            const int t   = (i / OCPT) % 9;
            const int ic  = i / (OCPT * 9);
            ws[i] = wsrc[((size_t)ocl * IC + ic) * 9 + t];
        }
    }
    __syncthreads();

    unsigned long long acc[NOP][PXC];
#pragma unroll
    for (int op = 0; op < NOP; op++)
#pragma unroll
        for (int p = 0; p < PXC; p++) acc[op][p] = 0ULL;

    const float* inb = in + (size_t)b * IC * planeI;

#pragma unroll 1
    for (int ic = 0; ic < IC; ic++) {
        const float* plane = inb + (size_t)ic * planeI;
#pragma unroll
        for (int ky = 0; ky < 3; ky++) {
            const float* rp = plane + (size_t)(oy * STRIDE + ky) * PWI
                                    + (size_t)x0 * STRIDE;
            unsigned long long pk[NIN];
            {
                float v[NV2 * 2];
#pragma unroll
                for (int i = 0; i < NV2; i++) {
                    const float2 t2 = *(const float2*)(rp + 2 * i);
                    v[2 * i]     = t2.x;
                    v[2 * i + 1] = t2.y;
                }
#pragma unroll
                for (int c = 0; c < NIN; c++) pk[c] = pack2(v[c]);
            }
#pragma unroll
            for (int kx = 0; kx < 3; kx++) {
                const float* wr = ws + (ic * 9 + ky * 3 + kx) * OCPT;
                unsigned long long w2[NOP];
#pragma unroll
                for (int j = 0; j < NF4; j++) {
                    const float4 wf = *(const float4*)(wr + 4 * j);
                    unsigned long long lo, hi;
                    asm("mov.b64 %0, {%1, %2};" : "=l"(lo)
                        : "f"(wf.x), "f"(wf.y));
                    asm("mov.b64 %0, {%1, %2};" : "=l"(hi)
                        : "f"(wf.z), "f"(wf.w));
                    w2[2 * j]     = lo;
                    w2[2 * j + 1] = hi;
                }
#pragma unroll
                for (int p = 0; p < PXC; p++) {
                    const unsigned long long xv = pk[p * STRIDE + kx];
#pragma unroll
                    for (int op = 0; op < NOP; op++)
                        FMA2(acc[op][p], w2[op], xv);
                }
            }
        }
    }

    const float inv = rsqrtf(1.f + 1e-5f);
#pragma unroll
    for (int op = 0; op < NOP; op++) {
        const int oc = g * OCPT + 2 * op;
        const float s0 = gamma[oc] * inv,  s1 = gamma[oc + 1] * inv;
        const float c0 = beta[oc],         c1 = beta[oc + 1];
        float* o0 = out + (size_t)(b * OC + oc) * planeO
                        + (size_t)(oy + 1) * PWO + 1;
        float* o1 = o0 + planeO;
#pragma unroll
        for (int p = 0; p < PXC; p++) {
            if (x0 + p < OW) {
                float2 a;
                memcpy(&a, &acc[op][p], 8);
                o0[x0 + p] = fmaxf(fmaf(a.x, s0, c0), 0.f);
                o1[x0 + p] = fmaxf(fmaf(a.y, s1, c1), 0.f);
            }
        }
    }
}

// ---------------------------------------------------------------------------
// DUAL-HEAD stride-1 conv: computes BOTH head convs (hm + depth hidden) from
// one set of input loads. OCPT channels per head per thread. Weights staged
// in ICB-channel SMEM chunks for both heads.
// ---------------------------------------------------------------------------
template<int IC, int OC, int OCPT, int PXC, int ICB>
__global__ void __launch_bounds__(128, 3)
convh(const float* __restrict__ in, int PWI, int planeI,
      int OH, int OW, int PWO, int planeO,
      const float* __restrict__ w0, const float* __restrict__ ga0,
      const float* __restrict__ be0, float* __restrict__ out0,
      const float* __restrict__ w1, const float* __restrict__ ga1,
      const float* __restrict__ be1, float* __restrict__ out1)
{
    constexpr int NG  = OC / OCPT;       // 12
    constexpr int NOP = OCPT / 2;        // 4
    constexpr int NF4 = NOP / 2;         // 2
    constexpr int NIN = PXC + 2;         // 8
    constexpr int NV2 = (NIN + 1) / 2;   // 4

    const int z = blockIdx.z;
    const int g = z % NG;
    const int b = z / NG;

    const int l  = threadIdx.x;
    const int oy = blockIdx.y * 4 + threadIdx.y;
    const int x0 = (blockIdx.x * 32 + l) * PXC;
    const int tid = threadIdx.y * 32 + l;

    __shared__ __align__(16) float ws[2][ICB * 9 * OCPT];

    unsigned long long acc[2][NOP][PXC];
#pragma unroll
    for (int h = 0; h < 2; h++)
#pragma unroll
        for (int op = 0; op < NOP; op++)
#pragma unroll
            for (int p = 0; p < PXC; p++) acc[h][op][p] = 0ULL;

    const float* inb = in + (size_t)b * IC * planeI;
    const size_t rowbase = (size_t)oy * PWI + (size_t)x0;

#pragma unroll 1
    for (int icb = 0; icb < IC; icb += ICB) {
        __syncthreads();
        for (int i = tid; i < ICB * 9 * OCPT; i += 128) {
            const int ocl = i % OCPT;
            const int t   = (i / OCPT) % 9;
            const int icr = i / (OCPT * 9);
            const size_t src = ((size_t)(g * OCPT + ocl) * IC + icb + icr) * 9 + t;
            ws[0][i] = w0[src];
            ws[1][i] = w1[src];
        }
        __syncthreads();

#pragma unroll 1
        for (int ic = 0; ic < ICB; ic++) {
            const float* plane = inb + (size_t)(icb + ic) * planeI + rowbase;
#pragma unroll
            for (int ky = 0; ky < 3; ky++) {
                const float* rp = plane + (size_t)ky * PWI;
                unsigned long long pk[NIN];
                {
                    float v[NV2 * 2];
#pragma unroll
                    for (int i = 0; i < NV2; i++) {
                        const float2 t2 = *(const float2*)(rp + 2 * i);
                        v[2 * i]     = t2.x;
                        v[2 * i + 1] = t2.y;
                    }
#pragma unroll
                    for (int c = 0; c < NIN; c++) pk[c] = pack2(v[c]);
                }
#pragma unroll
                for (int kx = 0; kx < 3; kx++) {
#pragma unroll
                    for (int h = 0; h < 2; h++) {
                        const float* wr = &ws[h][(ic * 9 + ky * 3 + kx) * OCPT];
                        unsigned long long w2[NOP];
#pragma unroll
                        for (int j = 0; j < NF4; j++) {
                            const float4 wf = *(const float4*)(wr + 4 * j);
                            unsigned long long lo, hi;
                            asm("mov.b64 %0, {%1, %2};" : "=l"(lo)
                                : "f"(wf.x), "f"(wf.y));
                            asm("mov.b64 %0, {%1, %2};" : "=l"(hi)
                                : "f"(wf.z), "f"(wf.w));
                            w2[2 * j]     = lo;
                            w2[2 * j + 1] = hi;
                        }
#pragma unroll
                        for (int p = 0; p < PXC; p++) {
                            const unsigned long long xv = pk[p + kx];
#pragma unroll
                            for (int op = 0; op < NOP; op++)
                                FMA2(acc[h][op][p], w2[op], xv);
                        }
                    }
                }
            }
        }
    }

    const float inv = rsqrtf(1.f + 1e-5f);
#pragma unroll
    for (int h = 0; h < 2; h++) {
        const float* gamma = h ? ga1 : ga0;
        const float* beta  = h ? be1 : be0;
        float*       out   = h ? out1 : out0;
#pragma unroll
        for (int op = 0; op < NOP; op++) {
            const int oc = g * OCPT + 2 * op;
            const float s0 = gamma[oc] * inv,  s1 = gamma[oc + 1] * inv;
            const float c0 = beta[oc],         c1 = beta[oc + 1];
            float* o0 = out + (size_t)(b * OC + oc) * planeO
                            + (size_t)(oy + 1) * PWO + 1;
            float* o1 = o0 + planeO;
#pragma unroll
            for (int p = 0; p < PXC; p++) {
                if (x0 + p < OW) {
                    float2 a;
                    memcpy(&a, &acc[h][op][p], 8);
                    o0[x0 + p] = fmaxf(fmaf(a.x, s0, c0), 0.f);
                    o1[x0 + p] = fmaxf(fmaf(a.y, s1, c1), 0.f);
                }
            }
        }
    }
}

// ---------------------------------------------------------------------------
// conv1 fused with padding: reads the RAW image. Interior threads take an
// unpredicated fast path; edge threads take the bounds-checked path.
// ---------------------------------------------------------------------------
template<int OCPT, int PXC>
__global__ void __launch_bounds__(128, 4)
conv1_raw(const float* __restrict__ img,
          const float* __restrict__ wgt, const float* __restrict__ gamma,
          const float* __restrict__ beta, float* __restrict__ out)
{
    constexpr int IC  = 3;
    constexpr int OC  = 32;
    constexpr int NG  = OC / OCPT;
    constexpr int NOP = OCPT / 2;
    constexpr int NF4 = NOP / 2;
    constexpr int NIN = (PXC - 1) * 2 + 3;   // 9 for PXC=4
    constexpr int OW  = 704;

    int z = blockIdx.z;
    const int g = z % NG;
    const int b = z / NG;

    const int l  = threadIdx.x;
    const int oy = blockIdx.y * 4 + threadIdx.y;
    const int x0 = (blockIdx.x * 32 + l) * PXC;

    __shared__ __align__(16) float ws[IC * 9 * OCPT];
    {
        const int tid = threadIdx.y * 32 + l;
        const float* wsrc = wgt + (size_t)(g * OCPT) * IC * 9;
        for (int i = tid; i < IC * 9 * OCPT; i += 128) {
            const int ocl = i % OCPT;
            const int t   = (i / OCPT) % 9;
            const int ic  = i / (OCPT * 9);
            ws[i] = wsrc[((size_t)ocl * IC + ic) * 9 + t];
        }
    }
    __syncthreads();

    unsigned long long acc[NOP][PXC];
#pragma unroll
    for (int op = 0; op < NOP; op++)
#pragma unroll
        for (int p = 0; p < PXC; p++) acc[op][p] = 0ULL;

    auto taps = [&](int ic, int ky, const unsigned long long (&pk)[NIN]) {
        const float* wbase = ws + (ic * 9 + ky * 3) * OCPT;
#pragma unroll
        for (int kx = 0; kx < 3; kx++) {
            const float* wr = wbase + kx * OCPT;
            unsigned long long w2[NOP];
#pragma unroll
            for (int j = 0; j < NF4; j++) {
                const float4 wf = *(const float4*)(wr + 4 * j);
                unsigned long long lo, hi;
                asm("mov.b64 %0, {%1, %2};" : "=l"(lo)
                    : "f"(wf.x), "f"(wf.y));
                asm("mov.b64 %0, {%1, %2};" : "=l"(hi)
                    : "f"(wf.z), "f"(wf.w));
                w2[2 * j]     = lo;
                w2[2 * j + 1] = hi;
            }
#pragma unroll
            for (int p = 0; p < PXC; p++) {
                const unsigned long long xv = pk[p * 2 + kx];
#pragma unroll
                for (int op = 0; op < NOP; op++)
                    FMA2(acc[op][p], w2[op], xv);
            }
        }
    };

    const bool fast = (oy >= 1) && (oy <= 254) && (x0 >= 1) && (x0 <= 700);

    if (fast) {
        const int ib = x0 * 2 - 2;
#pragma unroll
        for (int ic = 0; ic < IC; ic++) {
            const float* plane = img + (size_t)(b * IC + ic) * IMG_H * IMG_W;
#pragma unroll
            for (int ky = 0; ky < 3; ky++) {
                const float* row = plane + (size_t)(oy * 2 - 1 + ky) * IMG_W + ib;
                float v[10];
#pragma unroll
                for (int i = 0; i < 5; i++) {
                    const float2 t2 = *(const float2*)(row + 2 * i);
                    v[2 * i]     = t2.x;
                    v[2 * i + 1] = t2.y;
                }
                unsigned long long pk[NIN];
#pragma unroll
                for (int c = 0; c < NIN; c++) pk[c] = pack2(v[c + 1]);
                taps(ic, ky, pk);
            }
        }
    } else {
#pragma unroll
        for (int ic = 0; ic < IC; ic++) {
            const float* plane = img + (size_t)(b * IC + ic) * IMG_H * IMG_W;
#pragma unroll
            for (int ky = 0; ky < 3; ky++) {
                const int iy = oy * 2 - 1 + ky;
                const bool yok = (iy >= 0) & (iy < IMG_H);
                const float* row = plane + (size_t)iy * IMG_W;
                unsigned long long pk[NIN];
#pragma unroll
                for (int c = 0; c < NIN; c++) {
                    const int ix = x0 * 2 - 1 + c;
                    const float v = (yok && ix >= 0 && ix < IMG_W) ? row[ix]
                                                                   : 0.f;
                    pk[c] = pack2(v);
                }
                taps(ic, ky, pk);
            }
        }
    }

    const float inv = rsqrtf(1.f + 1e-5f);
#pragma unroll
    for (int op = 0; op < NOP; op++) {
        const int oc = g * OCPT + 2 * op;
        const float s0 = gamma[oc] * inv,  s1 = gamma[oc + 1] * inv;
        const float c0 = beta[oc],         c1 = beta[oc + 1];
        float* o0 = out + (size_t)(b * OC + oc) * PLANE1
                        + (size_t)(oy + 1) * PW1 + 1;
        float* o1 = o0 + PLANE1;
#pragma unroll
        for (int p = 0; p < PXC; p++) {
            if (x0 + p < OW) {
                float2 a;
                memcpy(&a, &acc[op][p], 8);
                o0[x0 + p] = fmaxf(fmaf(a.x, s0, c0), 0.f);
                o1[x0 + p] = fmaxf(fmaf(a.y, s1, c1), 0.f);
            }
        }
    }
}

// ---------------------------------------------------------------------------
// Both 1x1 heads in one launch: blockIdx.y = 0 -> hm logits from h1,
// blockIdx.y = 1 -> depth transform from d1.
// ---------------------------------------------------------------------------
__global__ void head1x1_both(const float* __restrict__ h1,
                             const float* __restrict__ d1,
                             const float* __restrict__ wh,
                             const float* __restrict__ bh,
                             const float* __restrict__ wd,
                             const float* __restrict__ bd,
                             float* __restrict__ out_hm,
                             float* __restrict__ out_depth)
{
    const int idx = blockIdx.x * blockDim.x + threadIdx.x;
    if (idx >= BATCH * NPIX) return;
    const int mode = blockIdx.y;
    const int b = idx / NPIX;
    const int p = idx % NPIX;
    const int y = p / FW;
    const int x = p % FW;

    const float* feat = mode ? d1 : h1;
    const float* w    = mode ? wd : wh;
    float s           = mode ? bd[0] : bh[0];

    const float* fb = feat + (size_t)b * 96 * PLANE3
                           + (size_t)(y + 1) * PW3 + (x + 1);
#pragma unroll 8
    for (int ic = 0; ic < 96; ic++)
        s += fb[(size_t)ic * PLANE3] * w[ic];

    if (mode == 0) {
        out_hm[idx] = s;
    } else {
        const float sig = 1.f / (1.f + expf(-s));
        out_depth[idx] = 1.0f + sig * 79.0f;
    }
}

// ---------------------------------------------------------------------------
// Projection + 5x5 Gaussian max-splat for one detection
// ---------------------------------------------------------------------------
__device__ __forceinline__ void splat_one(int b, int idx, float score,
                                          const float* __restrict__ depth,
                                          const float* __restrict__ P,
                                          const float* __restrict__ T,
                                          float* __restrict__ bev)
{
    if (score < THR) return;
    const int ys = idx / FW;
    const int xs = idx % FW;
    const float d = depth[b * NPIX + idx];
    const float u = (xs + 0.5f) * ((float)IMG_W / (float)FW);
    const float v = (ys + 0.5f) * ((float)IMG_H / (float)FH);

    const float* Pb = P + b * 12;
    const float fx = fmaxf(Pb[0], EPSV);
    const float fy = fmaxf(Pb[5], EPSV);
    const float cx = Pb[2], cy = Pb[6];
    const float tx = Pb[3], ty = Pb[7];
    const float xc = (u * d - cx * d - tx) / fx;
    const float yc = (v * d - cy * d - ty) / fy;

    const float* Tb = T + b * 16;
    const float lx = Tb[0]*xc + Tb[1]*yc + Tb[2]*d + Tb[3];
    const float ly = Tb[4]*xc + Tb[5]*yc + Tb[6]*d + Tb[7];

    const int gx = (int)floorf((lx + 51.2f) / 0.2f);
    const int gy = (int)floorf((ly + 51.2f) / 0.2f);

    if (gx < 0 || gx >= BEV || gy < 0 || gy >= BEV) return;

    const float isig = 18.f / 25.f;
    float* bb = bev + (size_t)b * BEV * BEV;
#pragma unroll
    for (int dy = -2; dy <= 2; dy++) {
        const int iy = gy + dy;
        if (iy < 0 || iy >= BEV) continue;
#pragma unroll
        for (int dx = -2; dx <= 2; dx++) {
            const int ix = gx + dx;
            if (ix < 0 || ix >= BEV) continue;
            const float val = score * expf(-(float)(dy*dy + dx*dx) * isig);
            atomicMax((int*)&bb[iy * BEV + ix], __float_as_int(val));
        }
    }
}

// ---------------------------------------------------------------------------
// Per-batch top-200 via 4-pass radix select + parallel splat.
// Block b also zeroes its own BEV plane first (fused zero_bev).
// ---------------------------------------------------------------------------
#define EQCAP 256
__global__ void __launch_bounds__(1024, 1)
topk_splat(const float* __restrict__ hm,
           const float* __restrict__ depth,
           const float* __restrict__ P,
           const float* __restrict__ T,
           float* __restrict__ bev)
{
    const int b   = blockIdx.x;
    const int tid = threadIdx.x;

    __shared__ float prob[NPIX];
    __shared__ unsigned cnt[256];
    __shared__ int eq[EQCAP];
    __shared__ int eq_n;
    __shared__ unsigned s_prefix;
    __shared__ int s_need;

    {
        float4* plane4 = (float4*)(bev + (size_t)b * BEV * BEV);
        const float4 z4 = make_float4(0.f, 0.f, 0.f, 0.f);
        for (int i = tid; i < BEV * BEV / 4; i += 1024) plane4[i] = z4;
    }

    for (int i = tid; i < NPIX; i += 1024) {
        const float x = hm[b * NPIX + i];
        prob[i] = 1.f / (1.f + expf(-x));
    }
    if (tid == 0) { s_prefix = 0u; s_need = TOPK; eq_n = 0; }
    __syncthreads();

    for (int pass = 0; pass < 4; pass++) {
        const int shift = 24 - 8 * pass;
        const unsigned pm = (pass == 0) ? 0u : (0xFFFFFFFFu << (32 - 8 * pass));
        if (tid < 256) cnt[tid] = 0;
        __syncthreads();
        const unsigned pref = s_prefix;
        for (int i = tid; i < NPIX; i += 1024) {
            const unsigned u = __float_as_uint(prob[i]);
            if ((u & pm) == pref)
                atomicAdd(&cnt[(u >> shift) & 255u], 1u);
        }
        __syncthreads();
        if (tid == 0) {
            int c = 0;
            const int nb = s_need;
            for (int bb = 255; bb >= 0; bb--) {
                const int cb = (int)cnt[bb];
                if (c + cb >= nb) {
                    s_prefix |= (unsigned)bb << shift;
                    s_need = nb - c;
                    break;
                }
                c += cb;
            }
        }
        __syncthreads();
    }

    const unsigned v200 = s_prefix;

    for (int i = tid; i < NPIX; i += 1024) {
        const unsigned u = __float_as_uint(prob[i]);
        if (u > v200) {
            splat_one(b, i, prob[i], depth, P, T, bev);
        } else if (u == v200) {
            const int p = atomicAdd(&eq_n, 1);
            if (p < EQCAP) eq[p] = i;
        }
    }
    __syncthreads();

    if (tid == 0) {
        const int n = (eq_n < EQCAP) ? eq_n : EQCAP;
        const int need = (s_need < n) ? s_need : n;
        for (int k = 0; k < need; k++) {
            int mi = k;
            for (int j = k + 1; j < n; j++)
                if (eq[j] < eq[mi]) mi = j;
            const int t = eq[k]; eq[k] = eq[mi]; eq[mi] = t;
        }
    }
    __syncthreads();

    if (tid < s_need && tid < EQCAP && tid < eq_n) {
        const int i = eq[tid];
        splat_one(b, i, prob[i], depth, P, T, bev);
    }
}

// ---------------------------------------------------------------------------
// Finalize: clip to prob, compute logits. Fast path for untouched cells.
// ---------------------------------------------------------------------------
__global__ void finalize_bev(float* __restrict__ out)
{
    const int i = blockIdx.x * blockDim.x + threadIdx.x;
    if (i >= BEV_SZ) return;
    float p = out[OFF_PROB + i];
    if (p <= EPSV) {
        out[OFF_PROB + i]   = EPSV;
        out[OFF_LOGITS + i] = -9.2102404f;
    } else {
        p = fminf(p, 1.f - EPSV);
        out[OFF_PROB + i]   = p;
        out[OFF_LOGITS + i] = logf(p) - log1pf(-p);
    }
}

// ---------------------------------------------------------------------------
// Launcher
// ---------------------------------------------------------------------------
extern "C" void kernel_launch(void* const* d_in, const int* in_sizes, int n_in,
                              void* d_out, int out_size)
{
    (void)in_sizes; (void)n_in; (void)out_size;

    const float* image = (const float*)d_in[0];
    const float* P     = (const float*)d_in[1];
    const float* T     = (const float*)d_in[2];
    const float* W1  = (const float*)d_in[3];
    const float* g1  = (const float*)d_in[4];
    const float* b1  = (const float*)d_in[5];
    const float* W2  = (const float*)d_in[6];
    const float* g2  = (const float*)d_in[7];
    const float* b2  = (const float*)d_in[8];
    const float* W3  = (const float*)d_in[9];
    const float* g3  = (const float*)d_in[10];
    const float* b3  = (const float*)d_in[11];
    const float* Wh1 = (const float*)d_in[12];
    const float* gh1 = (const float*)d_in[13];
    const float* bh1 = (const float*)d_in[14];
    const float* Wh2 = (const float*)d_in[15];
    const float* bh2 = (const float*)d_in[16];
    const float* Wd1 = (const float*)d_in[17];
    const float* gd1 = (const float*)d_in[18];
    const float* bd1 = (const float*)d_in[19];
    const float* Wd2 = (const float*)d_in[20];
    const float* bd2 = (const float*)d_in[21];

    float* out = (float*)d_out;

    float *x1, *x2, *feats, *h1, *d1;
    cudaGetSymbolAddress((void**)&x1,    g_x1);
    cudaGetSymbolAddress((void**)&x2,    g_x2);
    cudaGetSymbolAddress((void**)&feats, g_feats);
    cudaGetSymbolAddress((void**)&h1,    g_h1);
    cudaGetSymbolAddress((void**)&d1,    g_d1);

    dim3 blk(32, 4);

    // conv1 (pad fused, interior fast path): 3 -> 32, stride 2
    conv1_raw<16, 4><<<dim3(6, 64, BATCH * 2), blk>>>(image, W1, g1, b1, x1);

    // conv2: 32 -> 64, stride 2, OCPT=16, PXC=4 (proven config)
    convp<32, 64, 16, 2, 4><<<dim3(3, 32, BATCH * 4), blk>>>(
        x1, PW1, PLANE1, 128, 352, PW2, PLANE2, W2, g2, b2, x2);

    // conv3: 64 -> 96, stride 2, OCPT=12, PXC=6 (proven config)
    convp<64, 96, 12, 2, 6><<<dim3(1, 16, BATCH * 8), blk>>>(
        x2, PW2, PLANE2, 64, 176, PW3, PLANE3, W3, g3, b3, feats);

    // DUAL-HEAD hidden convs: both heads per block, OCPT=8 each, ICB=48
    convh<96, 96, 8, 6, 48><<<dim3(1, 16, BATCH * 12), blk>>>(
        feats, PW3, PLANE3, 64, 176, PW3, PLANE3,
        Wh1, gh1, bh1, h1, Wd1, gd1, bd1, d1);

    // both 1x1 heads in one launch
    head1x1_both<<<dim3((BATCH * NPIX + 255) / 256, 2), 256>>>(
        h1, d1, Wh2, bh2, Wd2, bd2, out + OFF_HM, out + OFF_DEPTH);

    // radix-select + splat (zeroes its own BEV plane), finalize
    topk_splat<<<BATCH, 1024>>>(out + OFF_HM, out + OFF_DEPTH, P, T, out + OFF_PROB);
    finalize_bev<<<(BEV_SZ + 255) / 256, 256>>>(out);
}

// round 14
// speedup vs baseline: 1.0126x; 1.0126x over previous
#include <cuda_runtime.h>
#include <cuda_bf16.h>
#include <math.h>
#include <string.h>

// ---------------------------------------------------------------------------
// Problem constants
// ---------------------------------------------------------------------------
#define BATCH 4
#define IMG_H 512
#define IMG_W 1408
#define FH 64
#define FW 176
#define NPIX (FH*FW)            // 11264
#define HM_SZ (BATCH*NPIX)      // 45056
#define BEV 512
#define BEV_SZ (BATCH*BEV*BEV)  // 1048576
#define TOPK 200
#define THR 0.15f
#define EPSV 1e-4f

#define OFF_HM     0
#define OFF_DEPTH  (HM_SZ)
#define OFF_LOGITS (2*HM_SZ)
#define OFF_PROB   (2*HM_SZ + BEV_SZ)

// Padded geometry (1-px halo, width padded to mult of 4)
#define PW1 708
#define PH1 258
#define PLANE1 (PH1*PW1)        // x1: 32 ch, 256x704
#define PW2 356
#define PH2 130
#define PLANE2 (PH2*PW2)        // x2: 64 ch, 128x352
#define PW3 180
#define PH3 66
#define PLANE3 (PH3*PW3)        // feats/h1/d1: 96 ch, 64x176

// ---------------------------------------------------------------------------
// Scratch (device globals: zero-initialized at module load; halos never
// written by any kernel, so they remain zero across all graph replays)
// ---------------------------------------------------------------------------
__device__ float g_x1[BATCH*32*PLANE1 + 4096];
__device__ float g_x2[BATCH*64*PLANE2 + 4096];
__device__ float g_feats[BATCH*96*PLANE3 + 4096];
__device__ float g_h1[BATCH*96*PLANE3 + 4096];
__device__ float g_d1[BATCH*96*PLANE3 + 4096];

// ---------------------------------------------------------------------------
// f32x2 packed math helpers
// ---------------------------------------------------------------------------
__device__ __forceinline__ unsigned long long pack2(float x) {
    unsigned long long r;
    const unsigned int u = __float_as_uint(x);
    asm("mov.b64 %0, {%1, %1};" : "=l"(r) : "r"(u));
    return r;
}
#define FMA2(acc, a, b) \
    asm("fma.rn.f32x2 %0, %1, %2, %0;" : "+l"(acc) : "l"(a), "l"(b))

// ---------------------------------------------------------------------------
// Padded direct 3x3 conv + BN(eval) + ReLU using packed f32x2 FMAs (R7 core).
// ---------------------------------------------------------------------------
template<int IC, int OC, int OCPT, int STRIDE, int PXC>
__global__ void __launch_bounds__(128, 4)
convp(const float* __restrict__ in, int PWI, int planeI,
      int OH, int OW, int PWO, int planeO,
      const float* __restrict__ wgt, const float* __restrict__ gamma,
      const float* __restrict__ beta, float* __restrict__ out)
{
    constexpr int NG  = OC / OCPT;
    constexpr int NOP = OCPT / 2;
    constexpr int NF4 = NOP / 2;
    constexpr int NIN = (PXC - 1) * STRIDE + 3;
    constexpr int NV2 = (NIN + 1) / 2;

    int z = blockIdx.z;
    const int g = z % NG;
    const int b = z / NG;

    const int l  = threadIdx.x;
    const int oy = blockIdx.y * 4 + threadIdx.y;
    const int x0 = (blockIdx.x * 32 + l) * PXC;

    __shared__ __align__(16) float ws[IC * 9 * OCPT];
    {
        const int tid = threadIdx.y * 32 + l;
        const float* wsrc = wgt + (size_t)(g * OCPT) * IC * 9;
        for (int i = tid; i < IC * 9 * OCPT; i += 128) {
            const int ocl = i % OCPT;
            const int t   = (i / OCPT) % 9;
            const int ic  = i / (OCPT * 9);
            ws[i] = wsrc[((size_t)ocl * IC + ic) * 9 + t];
        }
    }
    __syncthreads();

    unsigned long long acc[NOP][PXC];
#pragma unroll
    for (int op = 0; op < NOP; op++)
#pragma unroll
        for (int p = 0; p < PXC; p++) acc[op][p] = 0ULL;

    const float* inb = in + (size_t)b * IC * planeI;

#pragma unroll 1
    for (int ic = 0; ic < IC; ic++) {
        const float* plane = inb + (size_t)ic * planeI;
#pragma unroll
        for (int ky = 0; ky < 3; ky++) {
            const float* rp = plane + (size_t)(oy * STRIDE + ky) * PWI
                                    + (size_t)x0 * STRIDE;
            unsigned long long pk[NIN];
            {
                float v[NV2 * 2];
#pragma unroll
                for (int i = 0; i < NV2; i++) {
                    const float2 t2 = *(const float2*)(rp + 2 * i);
                    v[2 * i]     = t2.x;
                    v[2 * i + 1] = t2.y;
                }
#pragma unroll
                for (int c = 0; c < NIN; c++) pk[c] = pack2(v[c]);
            }
#pragma unroll
            for (int kx = 0; kx < 3; kx++) {
                const float* wr = ws + (ic * 9 + ky * 3 + kx) * OCPT;
                unsigned long long w2[NOP];
#pragma unroll
                for (int j = 0; j < NF4; j++) {
                    const float4 wf = *(const float4*)(wr + 4 * j);
                    unsigned long long lo, hi;
                    asm("mov.b64 %0, {%1, %2};" : "=l"(lo)
                        : "f"(wf.x), "f"(wf.y));
                    asm("mov.b64 %0, {%1, %2};" : "=l"(hi)
                        : "f"(wf.z), "f"(wf.w));
                    w2[2 * j]     = lo;
                    w2[2 * j + 1] = hi;
                }
#pragma unroll
                for (int p = 0; p < PXC; p++) {
                    const unsigned long long xv = pk[p * STRIDE + kx];
#pragma unroll
                    for (int op = 0; op < NOP; op++)
                        FMA2(acc[op][p], w2[op], xv);
                }
            }
        }
    }

    const float inv = rsqrtf(1.f + 1e-5f);
#pragma unroll
    for (int op = 0; op < NOP; op++) {
        const int oc = g * OCPT + 2 * op;
        const float s0 = gamma[oc] * inv,  s1 = gamma[oc + 1] * inv;
        const float c0 = beta[oc],         c1 = beta[oc + 1];
        float* o0 = out + (size_t)(b * OC + oc) * planeO
                        + (size_t)(oy + 1) * PWO + 1;
        float* o1 = o0 + planeO;
#pragma unroll
        for (int p = 0; p < PXC; p++) {
            if (x0 + p < OW) {
                float2 a;
                memcpy(&a, &acc[op][p], 8);
                o0[x0 + p] = fmaxf(fmaf(a.x, s0, c0), 0.f);
                o1[x0 + p] = fmaxf(fmaf(a.y, s1, c1), 0.f);
            }
        }
    }
}

// ---------------------------------------------------------------------------
// Stride-1 conv with FULL-CHANNEL prefetch ping-pong (head convs).
// PXC=3 -> x0 can be ODD, so input loads are SCALAR (alignment-safe).
// Small blocks (96 px) keep regs low -> 4 blocks/SM (16 warps) and finer
// wave quantization (2048 blocks).
// ---------------------------------------------------------------------------
template<int IC, int OC, int OCPT, int PXC, int DUAL>
__global__ void __launch_bounds__(128, 4)
convpf(const float* __restrict__ in, int PWI, int planeI,
       int OH, int OW, int PWO, int planeO,
       const float* __restrict__ w0, const float* __restrict__ ga0,
       const float* __restrict__ be0, float* __restrict__ out0,
       const float* __restrict__ w1, const float* __restrict__ ga1,
       const float* __restrict__ be1, float* __restrict__ out1)
{
    constexpr int NG  = OC / OCPT;
    constexpr int NOP = OCPT / 2;
    constexpr int NF4 = NOP / 2;
    constexpr int NIN = PXC + 2;

    int z = blockIdx.z;
    const int g = z % NG;  z /= NG;
    int head = 0;
    if (DUAL) { head = z & 1; z >>= 1; }
    const int b = z;

    const float* wgt   = (DUAL && head) ? w1  : w0;
    const float* gamma = (DUAL && head) ? ga1 : ga0;
    const float* beta  = (DUAL && head) ? be1 : be0;
    float*       out   = (DUAL && head) ? out1 : out0;

    const int l  = threadIdx.x;
    const int oy = blockIdx.y * 4 + threadIdx.y;
    const int x0 = (blockIdx.x * 32 + l) * PXC;

    __shared__ __align__(16) float ws[IC * 9 * OCPT];
    {
        const int tid = threadIdx.y * 32 + l;
        const float* wsrc = wgt + (size_t)(g * OCPT) * IC * 9;
        for (int i = tid; i < IC * 9 * OCPT; i += 128) {
            const int ocl = i % OCPT;
            const int t   = (i / OCPT) % 9;
            const int ic  = i / (OCPT * 9);
            ws[i] = wsrc[((size_t)ocl * IC + ic) * 9 + t];
        }
    }
    __syncthreads();

    unsigned long long acc[NOP][PXC];
#pragma unroll
    for (int op = 0; op < NOP; op++)
#pragma unroll
        for (int p = 0; p < PXC; p++) acc[op][p] = 0ULL;

    const float* inb = in + (size_t)b * IC * planeI;
    const size_t rowbase = (size_t)oy * PWI + (size_t)x0;

    float rawA[3][NIN], rawB[3][NIN];

    // scalar loads: alignment-safe for any x0
    auto loadch = [&](int ic_, float (*raw)[NIN]) {
        const float* plane = inb + (size_t)ic_ * planeI + rowbase;
#pragma unroll
        for (int ky = 0; ky < 3; ky++) {
            const float* rp = plane + (size_t)ky * PWI;
#pragma unroll
            for (int i = 0; i < NIN; i++) raw[ky][i] = rp[i];
        }
    };

    auto compute = [&](int ic_, float (*raw)[NIN]) {
        const float* wc = ws + ic_ * 9 * OCPT;
#pragma unroll
        for (int ky = 0; ky < 3; ky++) {
            unsigned long long pk[NIN];
#pragma unroll
            for (int c = 0; c < NIN; c++) pk[c] = pack2(raw[ky][c]);
#pragma unroll
            for (int kx = 0; kx < 3; kx++) {
                const float* wr = wc + (ky * 3 + kx) * OCPT;
                unsigned long long w2[NOP];
#pragma unroll
                for (int j = 0; j < NF4; j++) {
                    const float4 wf = *(const float4*)(wr + 4 * j);
                    unsigned long long lo, hi;
                    asm("mov.b64 %0, {%1, %2};" : "=l"(lo)
                        : "f"(wf.x), "f"(wf.y));
                    asm("mov.b64 %0, {%1, %2};" : "=l"(hi)
                        : "f"(wf.z), "f"(wf.w));
                    w2[2 * j]     = lo;
                    w2[2 * j + 1] = hi;
                }
#pragma unroll
                for (int p = 0; p < PXC; p++) {
                    const unsigned long long xv = pk[p + kx];
#pragma unroll
                    for (int op = 0; op < NOP; op++)
                        FMA2(acc[op][p], w2[op], xv);
                }
            }
        }
    };

    loadch(0, rawA);

#pragma unroll 1
    for (int ic = 0; ic < IC; ic += 2) {
        loadch(ic + 1, rawB);                           // prefetch odd channel
        compute(ic, rawA);
        loadch((ic + 2 < IC) ? ic + 2 : IC - 1, rawA);  // prefetch next even
        compute(ic + 1, rawB);
    }

    const float inv = rsqrtf(1.f + 1e-5f);
#pragma unroll
    for (int op = 0; op < NOP; op++) {
        const int oc = g * OCPT + 2 * op;
        const float s0 = gamma[oc] * inv,  s1 = gamma[oc + 1] * inv;
        const float c0 = beta[oc],         c1 = beta[oc + 1];
        float* o0 = out + (size_t)(b * OC + oc) * planeO
                        + (size_t)(oy + 1) * PWO + 1;
        float* o1 = o0 + planeO;
#pragma unroll
        for (int p = 0; p < PXC; p++) {
            if (x0 + p < OW) {
                float2 a;
                memcpy(&a, &acc[op][p], 8);
                o0[x0 + p] = fmaxf(fmaf(a.x, s0, c0), 0.f);
                o1[x0 + p] = fmaxf(fmaf(a.y, s1, c1), 0.f);
            }
        }
    }
}

// ---------------------------------------------------------------------------
// conv1 fused with padding: reads the RAW image (bounds-checked, zero-fill),
// writes into padded x1. IC=3, OC=32, stride 2.
// ---------------------------------------------------------------------------
template<int OCPT, int PXC>
__global__ void __launch_bounds__(128, 4)
conv1_raw(const float* __restrict__ img,
          const float* __restrict__ wgt, const float* __restrict__ gamma,
          const float* __restrict__ beta, float* __restrict__ out)
{
    constexpr int IC  = 3;
    constexpr int OC  = 32;
    constexpr int NG  = OC / OCPT;
    constexpr int NOP = OCPT / 2;
    constexpr int NF4 = NOP / 2;
    constexpr int NIN = (PXC - 1) * 2 + 3;
    constexpr int OW  = 704;

    int z = blockIdx.z;
    const int g = z % NG;
    const int b = z / NG;

    const int l  = threadIdx.x;
    const int oy = blockIdx.y * 4 + threadIdx.y;
    const int x0 = (blockIdx.x * 32 + l) * PXC;

    __shared__ __align__(16) float ws[IC * 9 * OCPT];
    {
        const int tid = threadIdx.y * 32 + l;
        const float* wsrc = wgt + (size_t)(g * OCPT) * IC * 9;
        for (int i = tid; i < IC * 9 * OCPT; i += 128) {
            const int ocl = i % OCPT;
            const int t   = (i / OCPT) % 9;
            const int ic  = i / (OCPT * 9);
            ws[i] = wsrc[((size_t)ocl * IC + ic) * 9 + t];
        }
    }
    __syncthreads();

    unsigned long long acc[NOP][PXC];
#pragma unroll
    for (int op = 0; op < NOP; op++)
#pragma unroll
        for (int p = 0; p < PXC; p++) acc[op][p] = 0ULL;

#pragma unroll
    for (int ic = 0; ic < IC; ic++) {
        const float* plane = img + (size_t)(b * IC + ic) * IMG_H * IMG_W;
#pragma unroll
        for (int ky = 0; ky < 3; ky++) {
            const int iy = oy * 2 - 1 + ky;
            const bool yok = (iy >= 0) & (iy < IMG_H);
            const float* row = plane + (size_t)iy * IMG_W;

            unsigned long long pk[NIN];
#pragma unroll
            for (int c = 0; c < NIN; c++) {
                const int ix = x0 * 2 - 1 + c;
                const float v = (yok && ix >= 0 && ix < IMG_W) ? row[ix] : 0.f;
                pk[c] = pack2(v);
            }
#pragma unroll
            for (int kx = 0; kx < 3; kx++) {
                const float* wr = ws + (ic * 9 + ky * 3 + kx) * OCPT;
                unsigned long long w2[NOP];
#pragma unroll
                for (int j = 0; j < NF4; j++) {
                    const float4 wf = *(const float4*)(wr + 4 * j);
                    unsigned long long lo, hi;
                    asm("mov.b64 %0, {%1, %2};" : "=l"(lo)
                        : "f"(wf.x), "f"(wf.y));
                    asm("mov.b64 %0, {%1, %2};" : "=l"(hi)
                        : "f"(wf.z), "f"(wf.w));
                    w2[2 * j]     = lo;
                    w2[2 * j + 1] = hi;
                }
#pragma unroll
                for (int p = 0; p < PXC; p++) {
                    const unsigned long long xv = pk[p * 2 + kx];
#pragma unroll
                    for (int op = 0; op < NOP; op++)
                        FMA2(acc[op][p], w2[op], xv);
                }
            }
        }
    }

    const float inv = rsqrtf(1.f + 1e-5f);
#pragma unroll
    for (int op = 0; op < NOP; op++) {
        const int oc = g * OCPT + 2 * op;
        const float s0 = gamma[oc] * inv,  s1 = gamma[oc + 1] * inv;
        const float c0 = beta[oc],         c1 = beta[oc + 1];
        float* o0 = out + (size_t)(b * OC + oc) * PLANE1
                        + (size_t)(oy + 1) * PW1 + 1;
        float* o1 = o0 + PLANE1;
#pragma unroll
        for (int p = 0; p < PXC; p++) {
            if (x0 + p < OW) {
                float2 a;
                memcpy(&a, &acc[op][p], 8);
                o0[x0 + p] = fmaxf(fmaf(a.x, s0, c0), 0.f);
                o1[x0 + p] = fmaxf(fmaf(a.y, s1, c1), 0.f);
            }
        }
    }
}

// ---------------------------------------------------------------------------
// 1x1 conv (96 -> 1) + bias (reads padded feature maps).
// ---------------------------------------------------------------------------
template<int MODE>
__global__ void head1x1(const float* __restrict__ feat,
                        const float* __restrict__ w,
                        const float* __restrict__ bias,
                        float* __restrict__ out)
{
    const int idx = blockIdx.x * blockDim.x + threadIdx.x;
    if (idx >= BATCH * NPIX) return;
    const int b = idx / NPIX;
    const int p = idx % NPIX;
    const int y = p / FW;
    const int x = p % FW;
    float s = bias[0];
    const float* fb = feat + (size_t)b * 96 * PLANE3
                           + (size_t)(y + 1) * PW3 + (x + 1);
#pragma unroll 8
    for (int ic = 0; ic < 96; ic++)
        s += fb[(size_t)ic * PLANE3] * w[ic];
    if (MODE == 0) {
        out[idx] = s;
    } else {
        const float sig = 1.f / (1.f + expf(-s));
        out[idx] = 1.0f + sig * 79.0f;
    }
}

// ---------------------------------------------------------------------------
// Zero the BEV accumulation region
// ---------------------------------------------------------------------------
__global__ void zero_bev(float* __restrict__ bev)
{
    const int i = blockIdx.x * blockDim.x + threadIdx.x;
    if (i < BEV_SZ) bev[i] = 0.f;
}

// ---------------------------------------------------------------------------
// Projection + 5x5 Gaussian max-splat for one detection
// ---------------------------------------------------------------------------
__device__ __forceinline__ void splat_one(int b, int idx, float score,
                                          const float* __restrict__ depth,
                                          const float* __restrict__ P,
                                          const float* __restrict__ T,
                                          float* __restrict__ bev)
{
    if (score < THR) return;
    const int ys = idx / FW;
    const int xs = idx % FW;
    const float d = depth[b * NPIX + idx];
    const float u = (xs + 0.5f) * ((float)IMG_W / (float)FW);
    const float v = (ys + 0.5f) * ((float)IMG_H / (float)FH);

    const float* Pb = P + b * 12;
    const float fx = fmaxf(Pb[0], EPSV);
    const float fy = fmaxf(Pb[5], EPSV);
    const float cx = Pb[2], cy = Pb[6];
    const float tx = Pb[3], ty = Pb[7];
    const float xc = (u * d - cx * d - tx) / fx;
    const float yc = (v * d - cy * d - ty) / fy;

    const float* Tb = T + b * 16;
    const float lx = Tb[0]*xc + Tb[1]*yc + Tb[2]*d + Tb[3];
    const float ly = Tb[4]*xc + Tb[5]*yc + Tb[6]*d + Tb[7];

    const int gx = (int)floorf((lx + 51.2f) / 0.2f);
    const int gy = (int)floorf((ly + 51.2f) / 0.2f);

    if (gx < 0 || gx >= BEV || gy < 0 || gy >= BEV) return;

    const float isig = 18.f / 25.f;
    float* bb = bev + (size_t)b * BEV * BEV;
#pragma unroll
    for (int dy = -2; dy <= 2; dy++) {
        const int iy = gy + dy;
        if (iy < 0 || iy >= BEV) continue;
#pragma unroll
        for (int dx = -2; dx <= 2; dx++) {
            const int ix = gx + dx;
            if (ix < 0 || ix >= BEV) continue;
            const float val = score * expf(-(float)(dy*dy + dx*dx) * isig);
            atomicMax((int*)&bb[iy * BEV + ix], __float_as_int(val));
        }
    }
}

// ---------------------------------------------------------------------------
// Per-batch top-200 via 4-pass radix select + parallel splat.
// ---------------------------------------------------------------------------
#define EQCAP 256
__global__ void __launch_bounds__(1024, 1)
topk_splat(const float* __restrict__ hm,
           const float* __restrict__ depth,
           const float* __restrict__ P,
           const float* __restrict__ T,
           float* __restrict__ bev)
{
    const int b   = blockIdx.x;
    const int tid = threadIdx.x;

    __shared__ float prob[NPIX];
    __shared__ unsigned cnt[256];
    __shared__ int eq[EQCAP];
    __shared__ int eq_n;
    __shared__ unsigned s_prefix;
    __shared__ int s_need;

    for (int i = tid; i < NPIX; i += 1024) {
        const float x = hm[b * NPIX + i];
        prob[i] = 1.f / (1.f + expf(-x));
    }
    if (tid == 0) { s_prefix = 0u; s_need = TOPK; eq_n = 0; }
    __syncthreads();

    for (int pass = 0; pass < 4; pass++) {
        const int shift = 24 - 8 * pass;
        const unsigned pm = (pass == 0) ? 0u : (0xFFFFFFFFu << (32 - 8 * pass));
        if (tid < 256) cnt[tid] = 0;
        __syncthreads();
        const unsigned pref = s_prefix;
        for (int i = tid; i < NPIX; i += 1024) {
            const unsigned u = __float_as_uint(prob[i]);
            if ((u & pm) == pref)
                atomicAdd(&cnt[(u >> shift) & 255u], 1u);
        }
        __syncthreads();
        if (tid == 0) {
            int c = 0;
            const int nb = s_need;
            for (int bb = 255; bb >= 0; bb--) {
                const int cb = (int)cnt[bb];
                if (c + cb >= nb) {
                    s_prefix |= (unsigned)bb << shift;
                    s_need = nb - c;
                    break;
                }
                c += cb;
            }
        }
        __syncthreads();
    }

    const unsigned v200 = s_prefix;

    for (int i = tid; i < NPIX; i += 1024) {
        const unsigned u = __float_as_uint(prob[i]);
        if (u > v200) {
            splat_one(b, i, prob[i], depth, P, T, bev);
        } else if (u == v200) {
            const int p = atomicAdd(&eq_n, 1);
            if (p < EQCAP) eq[p] = i;
        }
    }
    __syncthreads();

    if (tid == 0) {
        const int n = (eq_n < EQCAP) ? eq_n : EQCAP;
        const int need = (s_need < n) ? s_need : n;
        for (int k = 0; k < need; k++) {
            int mi = k;
            for (int j = k + 1; j < n; j++)
                if (eq[j] < eq[mi]) mi = j;
            const int t = eq[k]; eq[k] = eq[mi]; eq[mi] = t;
        }
    }
    __syncthreads();

    if (tid < s_need && tid < EQCAP && tid < eq_n) {
        const int i = eq[tid];
        splat_one(b, i, prob[i], depth, P, T, bev);
    }
}

// ---------------------------------------------------------------------------
// Finalize: clip to prob, compute logits. Fast path for untouched cells.
// ---------------------------------------------------------------------------
__global__ void finalize_bev(float* __restrict__ out)
{
    const int i = blockIdx.x * blockDim.x + threadIdx.x;
    if (i >= BEV_SZ) return;
    float p = out[OFF_PROB + i];
    if (p <= EPSV) {
        out[OFF_PROB + i]   = EPSV;
        out[OFF_LOGITS + i] = -9.2102404f;
    } else {
        p = fminf(p, 1.f - EPSV);
        out[OFF_PROB + i]   = p;
        out[OFF_LOGITS + i] = logf(p) - log1pf(-p);
    }
}

// ---------------------------------------------------------------------------
// Launcher
// ---------------------------------------------------------------------------
extern "C" void kernel_launch(void* const* d_in, const int* in_sizes, int n_in,
                              void* d_out, int out_size)
{
    (void)in_sizes; (void)n_in; (void)out_size;

    const float* image = (const float*)d_in[0];
    const float* P     = (const float*)d_in[1];
    const float* T     = (const float*)d_in[2];
    const float* W1  = (const float*)d_in[3];
    const float* g1  = (const float*)d_in[4];
    const float* b1  = (const float*)d_in[5];
    const float* W2  = (const float*)d_in[6];
    const float* g2  = (const float*)d_in[7];
    const float* b2  = (const float*)d_in[8];
    const float* W3  = (const float*)d_in[9];
    const float* g3  = (const float*)d_in[10];
    const float* b3  = (const float*)d_in[11];
    const float* Wh1 = (const float*)d_in[12];
    const float* gh1 = (const float*)d_in[13];
    const float* bh1 = (const float*)d_in[14];
    const float* Wh2 = (const float*)d_in[15];
    const float* bh2 = (const float*)d_in[16];
    const float* Wd1 = (const float*)d_in[17];
    const float* gd1 = (const float*)d_in[18];
    const float* bd1 = (const float*)d_in[19];
    const float* Wd2 = (const float*)d_in[20];
    const float* bd2 = (const float*)d_in[21];

    float* out = (float*)d_out;

    float *x1, *x2, *feats, *h1, *d1;
    cudaGetSymbolAddress((void**)&x1,    g_x1);
    cudaGetSymbolAddress((void**)&x2,    g_x2);
    cudaGetSymbolAddress((void**)&feats, g_feats);
    cudaGetSymbolAddress((void**)&h1,    g_h1);
    cudaGetSymbolAddress((void**)&d1,    g_d1);

    dim3 blk(32, 4);

    // conv1 (pad fused): 3 -> 32, stride 2, OCPT=16, PXC=4
    conv1_raw<16, 4><<<dim3(6, 64, BATCH * 2), blk>>>(image, W1, g1, b1, x1);

    // conv2: 32 -> 64, stride 2, OCPT=16, PXC=4 (proven config)
    convp<32, 64, 16, 2, 4><<<dim3(3, 32, BATCH * 4), blk>>>(
        x1, PW1, PLANE1, 128, 352, PW2, PLANE2, W2, g2, b2, x2);

    // conv3: 64 -> 96, stride 2, OCPT=12, PXC=6 (proven config, 1 wave)
    convp<64, 96, 12, 2, 6><<<dim3(1, 16, BATCH * 8), blk>>>(
        x2, PW2, PLANE2, 64, 176, PW3, PLANE3, W3, g3, b3, feats);

    // both head hidden convs (fused, channel-prefetch pipelined):
    // 96 -> 96, stride 1, OCPT=12, PXC=3 (scalar loads, 2048 small blocks)
    convpf<96, 96, 12, 3, 1><<<dim3(2, 16, BATCH * 2 * 8), blk>>>(
        feats, PW3, PLANE3, 64, 176, PW3, PLANE3,
        Wh1, gh1, bh1, h1, Wd1, gd1, bd1, d1);

    // 1x1 heads
    head1x1<0><<<(BATCH * NPIX + 255) / 256, 256>>>(h1, Wh2, bh2, out + OFF_HM);
    head1x1<1><<<(BATCH * NPIX + 255) / 256, 256>>>(d1, Wd2, bd2, out + OFF_DEPTH);

    // BEV accumulate (prob region), radix-select + splat, finalize
    zero_bev<<<(BEV_SZ + 255) / 256, 256>>>(out + OFF_PROB);
    topk_splat<<<BATCH, 1024>>>(out + OFF_HM, out + OFF_DEPTH, P, T, out + OFF_PROB);
    finalize_bev<<<(BEV_SZ + 255) / 256, 256>>>(out);
}

// round 15
// speedup vs baseline: 1.0645x; 1.0513x over previous
#include <cuda_runtime.h>
#include <cuda_bf16.h>
#include <math.h>
#include <string.h>

// ---------------------------------------------------------------------------
// Problem constants
// ---------------------------------------------------------------------------
#define BATCH 4
#define IMG_H 512
#define IMG_W 1408
#define FH 64
#define FW 176
#define NPIX (FH*FW)            // 11264
#define HM_SZ (BATCH*NPIX)      // 45056
#define BEV 512
#define BEV_SZ (BATCH*BEV*BEV)  // 1048576
#define TOPK 200
#define THR 0.15f
#define EPSV 1e-4f

#define OFF_HM     0
#define OFF_DEPTH  (HM_SZ)
#define OFF_LOGITS (2*HM_SZ)
#define OFF_PROB   (2*HM_SZ + BEV_SZ)

// Padded geometry (1-px halo, width padded to mult of 4)
#define PW1 708
#define PH1 258
#define PLANE1 (PH1*PW1)        // x1: 32 ch, 256x704
#define PW2 356
#define PH2 130
#define PLANE2 (PH2*PW2)        // x2: 64 ch, 128x352
#define PW3 180
#define PH3 66
#define PLANE3 (PH3*PW3)        // feats/h1/d1: 96 ch, 64x176

// ---------------------------------------------------------------------------
// Scratch (device globals: zero-initialized at module load; halos never
// written by any kernel, so they remain zero across all graph replays)
// ---------------------------------------------------------------------------
__device__ float g_x1[BATCH*32*PLANE1 + 4096];
__device__ float g_x2[BATCH*64*PLANE2 + 4096];
__device__ float g_feats[BATCH*96*PLANE3 + 4096];
__device__ float g_h1[BATCH*96*PLANE3 + 4096];
__device__ float g_d1[BATCH*96*PLANE3 + 4096];

// ---------------------------------------------------------------------------
// f32x2 packed math helpers
// ---------------------------------------------------------------------------
__device__ __forceinline__ unsigned long long pack2(float x) {
    unsigned long long r;
    const unsigned int u = __float_as_uint(x);
    asm("mov.b64 %0, {%1, %1};" : "=l"(r) : "r"(u));
    return r;
}
#define FMA2(acc, a, b) \
    asm("fma.rn.f32x2 %0, %1, %2, %0;" : "+l"(acc) : "l"(a), "l"(b))

// ---------------------------------------------------------------------------
// Padded direct 3x3 conv + BN(eval) + ReLU using packed f32x2 FMAs (R7 core).
// ---------------------------------------------------------------------------
template<int IC, int OC, int OCPT, int STRIDE, int PXC, int DUAL>
__global__ void __launch_bounds__(128, 4)
convp(const float* __restrict__ in, int PWI, int planeI,
      int OH, int OW, int PWO, int planeO,
      const float* __restrict__ w0, const float* __restrict__ ga0,
      const float* __restrict__ be0, float* __restrict__ out0,
      const float* __restrict__ w1, const float* __restrict__ ga1,
      const float* __restrict__ be1, float* __restrict__ out1)
{
    constexpr int NG  = OC / OCPT;
    constexpr int NOP = OCPT / 2;
    constexpr int NF4 = NOP / 2;
    constexpr int NIN = (PXC - 1) * STRIDE + 3;
    constexpr int NV2 = (NIN + 1) / 2;

    int z = blockIdx.z;
    const int g = z % NG;  z /= NG;
    int head = 0;
    if (DUAL) { head = z & 1; z >>= 1; }
    const int b = z;

    const float* wgt   = (DUAL && head) ? w1  : w0;
    const float* gamma = (DUAL && head) ? ga1 : ga0;
    const float* beta  = (DUAL && head) ? be1 : be0;
    float*       out   = (DUAL && head) ? out1 : out0;

    const int l  = threadIdx.x;
    const int oy = blockIdx.y * 4 + threadIdx.y;
    const int x0 = (blockIdx.x * 32 + l) * PXC;

    __shared__ __align__(16) float ws[IC * 9 * OCPT];
    {
        const int tid = threadIdx.y * 32 + l;
        const float* wsrc = wgt + (size_t)(g * OCPT) * IC * 9;
        for (int i = tid; i < IC * 9 * OCPT; i += 128) {
            const int ocl = i % OCPT;
            const int t   = (i / OCPT) % 9;
            const int ic  = i / (OCPT * 9);
            ws[i] = wsrc[((size_t)ocl * IC + ic) * 9 + t];
        }
    }
    __syncthreads();

    unsigned long long acc[NOP][PXC];
#pragma unroll
    for (int op = 0; op < NOP; op++)
#pragma unroll
        for (int p = 0; p < PXC; p++) acc[op][p] = 0ULL;

    const float* inb = in + (size_t)b * IC * planeI;

#pragma unroll 1
    for (int ic = 0; ic < IC; ic++) {
        const float* plane = inb + (size_t)ic * planeI;
#pragma unroll
        for (int ky = 0; ky < 3; ky++) {
            const float* rp = plane + (size_t)(oy * STRIDE + ky) * PWI
                                    + (size_t)x0 * STRIDE;
            unsigned long long pk[NIN];
            {
                float v[NV2 * 2];
#pragma unroll
                for (int i = 0; i < NV2; i++) {
                    const float2 t2 = *(const float2*)(rp + 2 * i);
                    v[2 * i]     = t2.x;
                    v[2 * i + 1] = t2.y;
                }
#pragma unroll
                for (int c = 0; c < NIN; c++) pk[c] = pack2(v[c]);
            }
#pragma unroll
            for (int kx = 0; kx < 3; kx++) {
                const float* wr = ws + (ic * 9 + ky * 3 + kx) * OCPT;
                unsigned long long w2[NOP];
#pragma unroll
                for (int j = 0; j < NF4; j++) {
                    const float4 wf = *(const float4*)(wr + 4 * j);
                    unsigned long long lo, hi;
                    asm("mov.b64 %0, {%1, %2};" : "=l"(lo)
                        : "f"(wf.x), "f"(wf.y));
                    asm("mov.b64 %0, {%1, %2};" : "=l"(hi)
                        : "f"(wf.z), "f"(wf.w));
                    w2[2 * j]     = lo;
                    w2[2 * j + 1] = hi;
                }
#pragma unroll
                for (int p = 0; p < PXC; p++) {
                    const unsigned long long xv = pk[p * STRIDE + kx];
#pragma unroll
                    for (int op = 0; op < NOP; op++)
                        FMA2(acc[op][p], w2[op], xv);
                }
            }
        }
    }

    const float inv = rsqrtf(1.f + 1e-5f);
#pragma unroll
    for (int op = 0; op < NOP; op++) {
        const int oc = g * OCPT + 2 * op;
        const float s0 = gamma[oc] * inv,  s1 = gamma[oc + 1] * inv;
        const float c0 = beta[oc],         c1 = beta[oc + 1];
        float* o0 = out + (size_t)(b * OC + oc) * planeO
                        + (size_t)(oy + 1) * PWO + 1;
        float* o1 = o0 + planeO;
#pragma unroll
        for (int p = 0; p < PXC; p++) {
            if (x0 + p < OW) {
                float2 a;
                memcpy(&a, &acc[op][p], 8);
                o0[x0 + p] = fmaxf(fmaf(a.x, s0, c0), 0.f);
                o1[x0 + p] = fmaxf(fmaf(a.y, s1, c1), 0.f);
            }
        }
    }
}

// ---------------------------------------------------------------------------
// Stride-1 conv with FULL-CHANNEL prefetch ping-pong (for the head convs).
// While channel ic's 9 taps execute (324 FMA2), the 3 input rows of channel
// ic+1 are already in flight into the alternate register buffer.
// ---------------------------------------------------------------------------
template<int IC, int OC, int OCPT, int PXC, int DUAL>
__global__ void __launch_bounds__(128, 3)
convpf(const float* __restrict__ in, int PWI, int planeI,
       int OH, int OW, int PWO, int planeO,
       const float* __restrict__ w0, const float* __restrict__ ga0,
       const float* __restrict__ be0, float* __restrict__ out0,
       const float* __restrict__ w1, const float* __restrict__ ga1,
       const float* __restrict__ be1, float* __restrict__ out1)
{
    constexpr int NG  = OC / OCPT;
    constexpr int NOP = OCPT / 2;
    constexpr int NF4 = NOP / 2;
    constexpr int NIN = PXC + 2;
    constexpr int NV2 = (NIN + 1) / 2;

    int z = blockIdx.z;
    const int g = z % NG;  z /= NG;
    int head = 0;
    if (DUAL) { head = z & 1; z >>= 1; }
    const int b = z;

    const float* wgt   = (DUAL && head) ? w1  : w0;
    const float* gamma = (DUAL && head) ? ga1 : ga0;
    const float* beta  = (DUAL && head) ? be1 : be0;
    float*       out   = (DUAL && head) ? out1 : out0;

    const int l  = threadIdx.x;
    const int oy = blockIdx.y * 4 + threadIdx.y;
    const int x0 = (blockIdx.x * 32 + l) * PXC;

    __shared__ __align__(16) float ws[IC * 9 * OCPT];
    {
        const int tid = threadIdx.y * 32 + l;
        const float* wsrc = wgt + (size_t)(g * OCPT) * IC * 9;
        for (int i = tid; i < IC * 9 * OCPT; i += 128) {
            const int ocl = i % OCPT;
            const int t   = (i / OCPT) % 9;
            const int ic  = i / (OCPT * 9);
            ws[i] = wsrc[((size_t)ocl * IC + ic) * 9 + t];
        }
    }
    __syncthreads();

    unsigned long long acc[NOP][PXC];
#pragma unroll
    for (int op = 0; op < NOP; op++)
#pragma unroll
        for (int p = 0; p < PXC; p++) acc[op][p] = 0ULL;

    const float* inb = in + (size_t)b * IC * planeI;
    const size_t rowbase = (size_t)oy * PWI + (size_t)x0;

    float rawA[3][NV2 * 2], rawB[3][NV2 * 2];

    auto loadch = [&](int ic_, float (*raw)[NV2 * 2]) {
        const float* plane = inb + (size_t)ic_ * planeI + rowbase;
#pragma unroll
        for (int ky = 0; ky < 3; ky++) {
            const float* rp = plane + (size_t)ky * PWI;
#pragma unroll
            for (int i = 0; i < NV2; i++) {
                const float2 t2 = *(const float2*)(rp + 2 * i);
                raw[ky][2 * i]     = t2.x;
                raw[ky][2 * i + 1] = t2.y;
            }
        }
    };

    auto compute = [&](int ic_, float (*raw)[NV2 * 2]) {
        const float* wc = ws + ic_ * 9 * OCPT;
#pragma unroll
        for (int ky = 0; ky < 3; ky++) {
            unsigned long long pk[NIN];
#pragma unroll
            for (int c = 0; c < NIN; c++) pk[c] = pack2(raw[ky][c]);
#pragma unroll
            for (int kx = 0; kx < 3; kx++) {
                const float* wr = wc + (ky * 3 + kx) * OCPT;
                unsigned long long w2[NOP];
#pragma unroll
                for (int j = 0; j < NF4; j++) {
                    const float4 wf = *(const float4*)(wr + 4 * j);
                    unsigned long long lo, hi;
                    asm("mov.b64 %0, {%1, %2};" : "=l"(lo)
                        : "f"(wf.x), "f"(wf.y));
                    asm("mov.b64 %0, {%1, %2};" : "=l"(hi)
                        : "f"(wf.z), "f"(wf.w));
                    w2[2 * j]     = lo;
                    w2[2 * j + 1] = hi;
                }
#pragma unroll
                for (int p = 0; p < PXC; p++) {
                    const unsigned long long xv = pk[p + kx];
#pragma unroll
                    for (int op = 0; op < NOP; op++)
                        FMA2(acc[op][p], w2[op], xv);
                }
            }
        }
    };

    loadch(0, rawA);

#pragma unroll 1
    for (int ic = 0; ic < IC; ic += 2) {
        loadch(ic + 1, rawB);                           // prefetch odd channel
        compute(ic, rawA);
        loadch((ic + 2 < IC) ? ic + 2 : IC - 1, rawA);  // prefetch next even
        compute(ic + 1, rawB);
    }

    const float inv = rsqrtf(1.f + 1e-5f);
#pragma unroll
    for (int op = 0; op < NOP; op++) {
        const int oc = g * OCPT + 2 * op;
        const float s0 = gamma[oc] * inv,  s1 = gamma[oc + 1] * inv;
        const float c0 = beta[oc],         c1 = beta[oc + 1];
        float* o0 = out + (size_t)(b * OC + oc) * planeO
                        + (size_t)(oy + 1) * PWO + 1;
        float* o1 = o0 + planeO;
#pragma unroll
        for (int p = 0; p < PXC; p++) {
            if (x0 + p < OW) {
                float2 a;
                memcpy(&a, &acc[op][p], 8);
                o0[x0 + p] = fmaxf(fmaf(a.x, s0, c0), 0.f);
                o1[x0 + p] = fmaxf(fmaf(a.y, s1, c1), 0.f);
            }
        }
    }
}

// ---------------------------------------------------------------------------
// conv1 fused with padding: reads the RAW image (bounds-checked, zero-fill),
// writes into padded x1. IC=3, OC=32, stride 2.
// ---------------------------------------------------------------------------
template<int OCPT, int PXC>
__global__ void __launch_bounds__(128, 4)
conv1_raw(const float* __restrict__ img,
          const float* __restrict__ wgt, const float* __restrict__ gamma,
          const float* __restrict__ beta, float* __restrict__ out)
{
    constexpr int IC  = 3;
    constexpr int OC  = 32;
    constexpr int NG  = OC / OCPT;
    constexpr int NOP = OCPT / 2;
    constexpr int NF4 = NOP / 2;
    constexpr int NIN = (PXC - 1) * 2 + 3;
    constexpr int OW  = 704;

    int z = blockIdx.z;
    const int g = z % NG;
    const int b = z / NG;

    const int l  = threadIdx.x;
    const int oy = blockIdx.y * 4 + threadIdx.y;
    const int x0 = (blockIdx.x * 32 + l) * PXC;

    __shared__ __align__(16) float ws[IC * 9 * OCPT];
    {
        const int tid = threadIdx.y * 32 + l;
        const float* wsrc = wgt + (size_t)(g * OCPT) * IC * 9;
        for (int i = tid; i < IC * 9 * OCPT; i += 128) {
            const int ocl = i % OCPT;
            const int t   = (i / OCPT) % 9;
            const int ic  = i / (OCPT * 9);
            ws[i] = wsrc[((size_t)ocl * IC + ic) * 9 + t];
        }
    }
    __syncthreads();

    unsigned long long acc[NOP][PXC];
#pragma unroll
    for (int op = 0; op < NOP; op++)
#pragma unroll
        for (int p = 0; p < PXC; p++) acc[op][p] = 0ULL;

#pragma unroll
    for (int ic = 0; ic < IC; ic++) {
        const float* plane = img + (size_t)(b * IC + ic) * IMG_H * IMG_W;
#pragma unroll
        for (int ky = 0; ky < 3; ky++) {
            const int iy = oy * 2 - 1 + ky;
            const bool yok = (iy >= 0) & (iy < IMG_H);
            const float* row = plane + (size_t)iy * IMG_W;

            unsigned long long pk[NIN];
#pragma unroll
            for (int c = 0; c < NIN; c++) {
                const int ix = x0 * 2 - 1 + c;
                const float v = (yok && ix >= 0 && ix < IMG_W) ? row[ix] : 0.f;
                pk[c] = pack2(v);
            }
#pragma unroll
            for (int kx = 0; kx < 3; kx++) {
                const float* wr = ws + (ic * 9 + ky * 3 + kx) * OCPT;
                unsigned long long w2[NOP];
#pragma unroll
                for (int j = 0; j < NF4; j++) {
                    const float4 wf = *(const float4*)(wr + 4 * j);
                    unsigned long long lo, hi;
                    asm("mov.b64 %0, {%1, %2};" : "=l"(lo)
                        : "f"(wf.x), "f"(wf.y));
                    asm("mov.b64 %0, {%1, %2};" : "=l"(hi)
                        : "f"(wf.z), "f"(wf.w));
                    w2[2 * j]     = lo;
                    w2[2 * j + 1] = hi;
                }
#pragma unroll
                for (int p = 0; p < PXC; p++) {
                    const unsigned long long xv = pk[p * 2 + kx];
#pragma unroll
                    for (int op = 0; op < NOP; op++)
                        FMA2(acc[op][p], w2[op], xv);
                }
            }
        }
    }

    const float inv = rsqrtf(1.f + 1e-5f);
#pragma unroll
    for (int op = 0; op < NOP; op++) {
        const int oc = g * OCPT + 2 * op;
        const float s0 = gamma[oc] * inv,  s1 = gamma[oc + 1] * inv;
        const float c0 = beta[oc],         c1 = beta[oc + 1];
        float* o0 = out + (size_t)(b * OC + oc) * PLANE1
                        + (size_t)(oy + 1) * PW1 + 1;
        float* o1 = o0 + PLANE1;
#pragma unroll
        for (int p = 0; p < PXC; p++) {
            if (x0 + p < OW) {
                float2 a;
                memcpy(&a, &acc[op][p], 8);
                o0[x0 + p] = fmaxf(fmaf(a.x, s0, c0), 0.f);
                o1[x0 + p] = fmaxf(fmaf(a.y, s1, c1), 0.f);
            }
        }
    }
}

// ---------------------------------------------------------------------------
// 1x1 conv (96 -> 1) + bias (reads padded feature maps).
// ---------------------------------------------------------------------------
template<int MODE>
__global__ void head1x1(const float* __restrict__ feat,
                        const float* __restrict__ w,
                        const float* __restrict__ bias,
                        float* __restrict__ out)
{
    const int idx = blockIdx.x * blockDim.x + threadIdx.x;
    if (idx >= BATCH * NPIX) return;
    const int b = idx / NPIX;
    const int p = idx % NPIX;
    const int y = p / FW;
    const int x = p % FW;
    float s = bias[0];
    const float* fb = feat + (size_t)b * 96 * PLANE3
                           + (size_t)(y + 1) * PW3 + (x + 1);
#pragma unroll 8
    for (int ic = 0; ic < 96; ic++)
        s += fb[(size_t)ic * PLANE3] * w[ic];
    if (MODE == 0) {
        out[idx] = s;
    } else {
        const float sig = 1.f / (1.f + expf(-s));
        out[idx] = 1.0f + sig * 79.0f;
    }
}

// ---------------------------------------------------------------------------
// Zero the BEV accumulation region
// ---------------------------------------------------------------------------
__global__ void zero_bev(float* __restrict__ bev)
{
    const int i = blockIdx.x * blockDim.x + threadIdx.x;
    if (i < BEV_SZ) bev[i] = 0.f;
}

// ---------------------------------------------------------------------------
// Projection + 5x5 Gaussian max-splat for one detection
// ---------------------------------------------------------------------------
__device__ __forceinline__ void splat_one(int b, int idx, float score,
                                          const float* __restrict__ depth,
                                          const float* __restrict__ P,
                                          const float* __restrict__ T,
                                          float* __restrict__ bev)
{
    if (score < THR) return;
    const int ys = idx / FW;
    const int xs = idx % FW;
    const float d = depth[b * NPIX + idx];
    const float u = (xs + 0.5f) * ((float)IMG_W / (float)FW);
    const float v = (ys + 0.5f) * ((float)IMG_H / (float)FH);

    const float* Pb = P + b * 12;
    const float fx = fmaxf(Pb[0], EPSV);
    const float fy = fmaxf(Pb[5], EPSV);
    const float cx = Pb[2], cy = Pb[6];
    const float tx = Pb[3], ty = Pb[7];
    const float xc = (u * d - cx * d - tx) / fx;
    const float yc = (v * d - cy * d - ty) / fy;

    const float* Tb = T + b * 16;
    const float lx = Tb[0]*xc + Tb[1]*yc + Tb[2]*d + Tb[3];
    const float ly = Tb[4]*xc + Tb[5]*yc + Tb[6]*d + Tb[7];

    const int gx = (int)floorf((lx + 51.2f) / 0.2f);
    const int gy = (int)floorf((ly + 51.2f) / 0.2f);

    if (gx < 0 || gx >= BEV || gy < 0 || gy >= BEV) return;

    const float isig = 18.f / 25.f;
    float* bb = bev + (size_t)b * BEV * BEV;
#pragma unroll
    for (int dy = -2; dy <= 2; dy++) {
        const int iy = gy + dy;
        if (iy < 0 || iy >= BEV) continue;
#pragma unroll
        for (int dx = -2; dx <= 2; dx++) {
            const int ix = gx + dx;
            if (ix < 0 || ix >= BEV) continue;
            const float val = score * expf(-(float)(dy*dy + dx*dx) * isig);
            atomicMax((int*)&bb[iy * BEV + ix], __float_as_int(val));
        }
    }
}

// ---------------------------------------------------------------------------
// Per-batch top-200 via 4-pass radix select + parallel splat.
// ---------------------------------------------------------------------------
#define EQCAP 256
__global__ void __launch_bounds__(1024, 1)
topk_splat(const float* __restrict__ hm,
           const float* __restrict__ depth,
           const float* __restrict__ P,
           const float* __restrict__ T,
           float* __restrict__ bev)
{
    const int b   = blockIdx.x;
    const int tid = threadIdx.x;

    __shared__ float prob[NPIX];
    __shared__ unsigned cnt[256];
    __shared__ int eq[EQCAP];
    __shared__ int eq_n;
    __shared__ unsigned s_prefix;
    __shared__ int s_need;

    for (int i = tid; i < NPIX; i += 1024) {
        const float x = hm[b * NPIX + i];
        prob[i] = 1.f / (1.f + expf(-x));
    }
    if (tid == 0) { s_prefix = 0u; s_need = TOPK; eq_n = 0; }
    __syncthreads();

    for (int pass = 0; pass < 4; pass++) {
        const int shift = 24 - 8 * pass;
        const unsigned pm = (pass == 0) ? 0u : (0xFFFFFFFFu << (32 - 8 * pass));
        if (tid < 256) cnt[tid] = 0;
        __syncthreads();
        const unsigned pref = s_prefix;
        for (int i = tid; i < NPIX; i += 1024) {
            const unsigned u = __float_as_uint(prob[i]);
            if ((u & pm) == pref)
                atomicAdd(&cnt[(u >> shift) & 255u], 1u);
        }
        __syncthreads();
        if (tid == 0) {
            int c = 0;
            const int nb = s_need;
            for (int bb = 255; bb >= 0; bb--) {
                const int cb = (int)cnt[bb];
                if (c + cb >= nb) {
                    s_prefix |= (unsigned)bb << shift;
                    s_need = nb - c;
                    break;
                }
                c += cb;
            }
        }
        __syncthreads();
    }

    const unsigned v200 = s_prefix;

    for (int i = tid; i < NPIX; i += 1024) {
        const unsigned u = __float_as_uint(prob[i]);
        if (u > v200) {
            splat_one(b, i, prob[i], depth, P, T, bev);
        } else if (u == v200) {
            const int p = atomicAdd(&eq_n, 1);
            if (p < EQCAP) eq[p] = i;
        }
    }
    __syncthreads();

    if (tid == 0) {
        const int n = (eq_n < EQCAP) ? eq_n : EQCAP;
        const int need = (s_need < n) ? s_need : n;
        for (int k = 0; k < need; k++) {
            int mi = k;
            for (int j = k + 1; j < n; j++)
                if (eq[j] < eq[mi]) mi = j;
            const int t = eq[k]; eq[k] = eq[mi]; eq[mi] = t;
        }
    }
    __syncthreads();

    if (tid < s_need && tid < EQCAP && tid < eq_n) {
        const int i = eq[tid];
        splat_one(b, i, prob[i], depth, P, T, bev);
    }
}

// ---------------------------------------------------------------------------
// Finalize: clip to prob, compute logits. Fast path for untouched cells.
// ---------------------------------------------------------------------------
__global__ void finalize_bev(float* __restrict__ out)
{
    const int i = blockIdx.x * blockDim.x + threadIdx.x;
    if (i >= BEV_SZ) return;
    float p = out[OFF_PROB + i];
    if (p <= EPSV) {
        out[OFF_PROB + i]   = EPSV;
        out[OFF_LOGITS + i] = -9.2102404f;
    } else {
        p = fminf(p, 1.f - EPSV);
        out[OFF_PROB + i]   = p;
        out[OFF_LOGITS + i] = logf(p) - log1pf(-p);
    }
}

// ---------------------------------------------------------------------------
// Launcher
// ---------------------------------------------------------------------------
extern "C" void kernel_launch(void* const* d_in, const int* in_sizes, int n_in,
                              void* d_out, int out_size)
{
    (void)in_sizes; (void)n_in; (void)out_size;

    const float* image = (const float*)d_in[0];
    const float* P     = (const float*)d_in[1];
    const float* T     = (const float*)d_in[2];
    const float* W1  = (const float*)d_in[3];
    const float* g1  = (const float*)d_in[4];
    const float* b1  = (const float*)d_in[5];
    const float* W2  = (const float*)d_in[6];
    const float* g2  = (const float*)d_in[7];
    const float* b2  = (const float*)d_in[8];
    const float* W3  = (const float*)d_in[9];
    const float* g3  = (const float*)d_in[10];
    const float* b3  = (const float*)d_in[11];
    const float* Wh1 = (const float*)d_in[12];
    const float* gh1 = (const float*)d_in[13];
    const float* bh1 = (const float*)d_in[14];
    const float* Wh2 = (const float*)d_in[15];
    const float* bh2 = (const float*)d_in[16];
    const float* Wd1 = (const float*)d_in[17];
    const float* gd1 = (const float*)d_in[18];
    const float* bd1 = (const float*)d_in[19];
    const float* Wd2 = (const float*)d_in[20];
    const float* bd2 = (const float*)d_in[21];

    float* out = (float*)d_out;

    float *x1, *x2, *feats, *h1, *d1;
    cudaGetSymbolAddress((void**)&x1,    g_x1);
    cudaGetSymbolAddress((void**)&x2,    g_x2);
    cudaGetSymbolAddress((void**)&feats, g_feats);
    cudaGetSymbolAddress((void**)&h1,    g_h1);
    cudaGetSymbolAddress((void**)&d1,    g_d1);

    dim3 blk(32, 4);

    // conv1 (pad fused): 3 -> 32, stride 2, OCPT=16, PXC=4
    conv1_raw<16, 4><<<dim3(6, 64, BATCH * 2), blk>>>(image, W1, g1, b1, x1);

    // conv2: 32 -> 64, stride 2, OCPT=16, PXC=4
    convp<32, 64, 16, 2, 4, 0><<<dim3(3, 32, BATCH * 4), blk>>>(
        x1, PW1, PLANE1, 128, 352, PW2, PLANE2,
        W2, g2, b2, x2, nullptr, nullptr, nullptr, nullptr);

    // conv3: 64 -> 96, stride 2, OCPT=12, PXC=6
    convp<64, 96, 12, 2, 6, 0><<<dim3(1, 16, BATCH * 8), blk>>>(
        x2, PW2, PLANE2, 64, 176, PW3, PLANE3,
        W3, g3, b3, feats, nullptr, nullptr, nullptr, nullptr);

    // both head hidden convs (fused, channel-prefetch pipelined):
    // 96 -> 96, stride 1, OCPT=12, PXC=6
    convpf<96, 96, 12, 6, 1><<<dim3(1, 16, BATCH * 2 * 8), blk>>>(
        feats, PW3, PLANE3, 64, 176, PW3, PLANE3,
        Wh1, gh1, bh1, h1, Wd1, gd1, bd1, d1);

    // 1x1 heads
    head1x1<0><<<(BATCH * NPIX + 255) / 256, 256>>>(h1, Wh2, bh2, out + OFF_HM);
    head1x1<1><<<(BATCH * NPIX + 255) / 256, 256>>>(d1, Wd2, bd2, out + OFF_DEPTH);

    // BEV accumulate (prob region), radix-select + splat, finalize
    zero_bev<<<(BEV_SZ + 255) / 256, 256>>>(out + OFF_PROB);
    topk_splat<<<BATCH, 1024>>>(out + OFF_HM, out + OFF_DEPTH, P, T, out + OFF_PROB);
    finalize_bev<<<(BEV_SZ + 255) / 256, 256>>>(out);
}

// round 16
// speedup vs baseline: 1.0682x; 1.0034x over previous
#include <cuda_runtime.h>
#include <cuda_bf16.h>
#include <math.h>
#include <string.h>

// ---------------------------------------------------------------------------
// Problem constants
// ---------------------------------------------------------------------------
#define BATCH 4
#define IMG_H 512
#define IMG_W 1408
#define FH 64
#define FW 176
#define NPIX (FH*FW)            // 11264
#define HM_SZ (BATCH*NPIX)      // 45056
#define BEV 512
#define BEV_SZ (BATCH*BEV*BEV)  // 1048576
#define TOPK 200
#define THR 0.15f
#define EPSV 1e-4f

#define OFF_HM     0
#define OFF_DEPTH  (HM_SZ)
#define OFF_LOGITS (2*HM_SZ)
#define OFF_PROB   (2*HM_SZ + BEV_SZ)

// Padded geometry (1-px halo, width padded to mult of 4)
#define PW1 708
#define PH1 258
#define PLANE1 (PH1*PW1)        // x1: 32 ch, 256x704
#define PW2 356
#define PH2 130
#define PLANE2 (PH2*PW2)        // x2: 64 ch, 128x352
#define PW3 180
#define PH3 66
#define PLANE3 (PH3*PW3)        // feats/h1/d1: 96 ch, 64x176

// ---------------------------------------------------------------------------
// Scratch (device globals: zero-initialized at module load; halos never
// written by any kernel, so they remain zero across all graph replays)
// ---------------------------------------------------------------------------
__device__ float g_x1[BATCH*32*PLANE1 + 4096];
__device__ float g_x2[BATCH*64*PLANE2 + 4096];
__device__ float g_feats[BATCH*96*PLANE3 + 4096];
__device__ float g_h1[BATCH*96*PLANE3 + 4096];
__device__ float g_d1[BATCH*96*PLANE3 + 4096];

// ---------------------------------------------------------------------------
// f32x2 packed math helpers
// ---------------------------------------------------------------------------
__device__ __forceinline__ unsigned long long pack2(float x) {
    unsigned long long r;
    const unsigned int u = __float_as_uint(x);
    asm("mov.b64 %0, {%1, %1};" : "=l"(r) : "r"(u));
    return r;
}
#define FMA2(acc, a, b) \
    asm("fma.rn.f32x2 %0, %1, %2, %0;" : "+l"(acc) : "l"(a), "l"(b))

// ---------------------------------------------------------------------------
// Padded direct 3x3 conv + BN(eval) + ReLU using packed f32x2 FMAs (R7 core).
// ---------------------------------------------------------------------------
template<int IC, int OC, int OCPT, int STRIDE, int PXC, int DUAL>
__global__ void __launch_bounds__(128, 4)
convp(const float* __restrict__ in, int PWI, int planeI,
      int OH, int OW, int PWO, int planeO,
      const float* __restrict__ w0, const float* __restrict__ ga0,
      const float* __restrict__ be0, float* __restrict__ out0,
      const float* __restrict__ w1, const float* __restrict__ ga1,
      const float* __restrict__ be1, float* __restrict__ out1)
{
    constexpr int NG  = OC / OCPT;
    constexpr int NOP = OCPT / 2;
    constexpr int NF4 = NOP / 2;
    constexpr int NIN = (PXC - 1) * STRIDE + 3;
    constexpr int NV2 = (NIN + 1) / 2;

    int z = blockIdx.z;
    const int g = z % NG;  z /= NG;
    int head = 0;
    if (DUAL) { head = z & 1; z >>= 1; }
    const int b = z;

    const float* wgt   = (DUAL && head) ? w1  : w0;
    const float* gamma = (DUAL && head) ? ga1 : ga0;
    const float* beta  = (DUAL && head) ? be1 : be0;
    float*       out   = (DUAL && head) ? out1 : out0;

    const int l  = threadIdx.x;
    const int oy = blockIdx.y * 4 + threadIdx.y;
    const int x0 = (blockIdx.x * 32 + l) * PXC;

    __shared__ __align__(16) float ws[IC * 9 * OCPT];
    {
        const int tid = threadIdx.y * 32 + l;
        const float* wsrc = wgt + (size_t)(g * OCPT) * IC * 9;
        for (int i = tid; i < IC * 9 * OCPT; i += 128) {
            const int ocl = i % OCPT;
            const int t   = (i / OCPT) % 9;
            const int ic  = i / (OCPT * 9);
            ws[i] = wsrc[((size_t)ocl * IC + ic) * 9 + t];
        }
    }
    __syncthreads();

    unsigned long long acc[NOP][PXC];
#pragma unroll
    for (int op = 0; op < NOP; op++)
#pragma unroll
        for (int p = 0; p < PXC; p++) acc[op][p] = 0ULL;

    const float* inb = in + (size_t)b * IC * planeI;

#pragma unroll 1
    for (int ic = 0; ic < IC; ic++) {
        const float* plane = inb + (size_t)ic * planeI;
#pragma unroll
        for (int ky = 0; ky < 3; ky++) {
            const float* rp = plane + (size_t)(oy * STRIDE + ky) * PWI
                                    + (size_t)x0 * STRIDE;
            unsigned long long pk[NIN];
            {
                float v[NV2 * 2];
#pragma unroll
                for (int i = 0; i < NV2; i++) {
                    const float2 t2 = *(const float2*)(rp + 2 * i);
                    v[2 * i]     = t2.x;
                    v[2 * i + 1] = t2.y;
                }
#pragma unroll
                for (int c = 0; c < NIN; c++) pk[c] = pack2(v[c]);
            }
#pragma unroll
            for (int kx = 0; kx < 3; kx++) {
                const float* wr = ws + (ic * 9 + ky * 3 + kx) * OCPT;
                unsigned long long w2[NOP];
#pragma unroll
                for (int j = 0; j < NF4; j++) {
                    const float4 wf = *(const float4*)(wr + 4 * j);
                    unsigned long long lo, hi;
                    asm("mov.b64 %0, {%1, %2};" : "=l"(lo)
                        : "f"(wf.x), "f"(wf.y));
                    asm("mov.b64 %0, {%1, %2};" : "=l"(hi)
                        : "f"(wf.z), "f"(wf.w));
                    w2[2 * j]     = lo;
                    w2[2 * j + 1] = hi;
                }
#pragma unroll
                for (int p = 0; p < PXC; p++) {
                    const unsigned long long xv = pk[p * STRIDE + kx];
#pragma unroll
                    for (int op = 0; op < NOP; op++)
                        FMA2(acc[op][p], w2[op], xv);
                }
            }
        }
    }

    const float inv = rsqrtf(1.f + 1e-5f);
#pragma unroll
    for (int op = 0; op < NOP; op++) {
        const int oc = g * OCPT + 2 * op;
        const float s0 = gamma[oc] * inv,  s1 = gamma[oc + 1] * inv;
        const float c0 = beta[oc],         c1 = beta[oc + 1];
        float* o0 = out + (size_t)(b * OC + oc) * planeO
                        + (size_t)(oy + 1) * PWO + 1;
        float* o1 = o0 + planeO;
#pragma unroll
        for (int p = 0; p < PXC; p++) {
            if (x0 + p < OW) {
                float2 a;
                memcpy(&a, &acc[op][p], 8);
                o0[x0 + p] = fmaxf(fmaf(a.x, s0, c0), 0.f);
                o1[x0 + p] = fmaxf(fmaf(a.y, s1, c1), 0.f);
            }
        }
    }
}

// ---------------------------------------------------------------------------
// Stride-1 conv with FULL-CHANNEL prefetch ping-pong (for the head convs).
// While channel ic's 9 taps execute (324 FMA2), the 3 input rows of channel
// ic+1 are already in flight into the alternate register buffer.
// ---------------------------------------------------------------------------
template<int IC, int OC, int OCPT, int PXC, int DUAL>
__global__ void __launch_bounds__(128, 3)
convpf(const float* __restrict__ in, int PWI, int planeI,
       int OH, int OW, int PWO, int planeO,
       const float* __restrict__ w0, const float* __restrict__ ga0,
       const float* __restrict__ be0, float* __restrict__ out0,
       const float* __restrict__ w1, const float* __restrict__ ga1,
       const float* __restrict__ be1, float* __restrict__ out1)
{
    constexpr int NG  = OC / OCPT;
    constexpr int NOP = OCPT / 2;
    constexpr int NF4 = NOP / 2;
    constexpr int NIN = PXC + 2;
    constexpr int NV2 = (NIN + 1) / 2;

    int z = blockIdx.z;
    const int g = z % NG;  z /= NG;
    int head = 0;
    if (DUAL) { head = z & 1; z >>= 1; }
    const int b = z;

    const float* wgt   = (DUAL && head) ? w1  : w0;
    const float* gamma = (DUAL && head) ? ga1 : ga0;
    const float* beta  = (DUAL && head) ? be1 : be0;
    float*       out   = (DUAL && head) ? out1 : out0;

    const int l  = threadIdx.x;
    const int oy = blockIdx.y * 4 + threadIdx.y;
    const int x0 = (blockIdx.x * 32 + l) * PXC;

    __shared__ __align__(16) float ws[IC * 9 * OCPT];
    {
        const int tid = threadIdx.y * 32 + l;
        const float* wsrc = wgt + (size_t)(g * OCPT) * IC * 9;
        for (int i = tid; i < IC * 9 * OCPT; i += 128) {
            const int ocl = i % OCPT;
            const int t   = (i / OCPT) % 9;
            const int ic  = i / (OCPT * 9);
            ws[i] = wsrc[((size_t)ocl * IC + ic) * 9 + t];
        }
    }
    __syncthreads();

    unsigned long long acc[NOP][PXC];
#pragma unroll
    for (int op = 0; op < NOP; op++)
#pragma unroll
        for (int p = 0; p < PXC; p++) acc[op][p] = 0ULL;

    const float* inb = in + (size_t)b * IC * planeI;
    const size_t rowbase = (size_t)oy * PWI + (size_t)x0;

    float rawA[3][NV2 * 2], rawB[3][NV2 * 2];

    auto loadch = [&](int ic_, float (*raw)[NV2 * 2]) {
        const float* plane = inb + (size_t)ic_ * planeI + rowbase;
#pragma unroll
        for (int ky = 0; ky < 3; ky++) {
            const float* rp = plane + (size_t)ky * PWI;
#pragma unroll
            for (int i = 0; i < NV2; i++) {
                const float2 t2 = *(const float2*)(rp + 2 * i);
                raw[ky][2 * i]     = t2.x;
                raw[ky][2 * i + 1] = t2.y;
            }
        }
    };

    auto compute = [&](int ic_, float (*raw)[NV2 * 2]) {
        const float* wc = ws + ic_ * 9 * OCPT;
#pragma unroll
        for (int ky = 0; ky < 3; ky++) {
            unsigned long long pk[NIN];
#pragma unroll
            for (int c = 0; c < NIN; c++) pk[c] = pack2(raw[ky][c]);
#pragma unroll
            for (int kx = 0; kx < 3; kx++) {
                const float* wr = wc + (ky * 3 + kx) * OCPT;
                unsigned long long w2[NOP];
#pragma unroll
                for (int j = 0; j < NF4; j++) {
                    const float4 wf = *(const float4*)(wr + 4 * j);
                    unsigned long long lo, hi;
                    asm("mov.b64 %0, {%1, %2};" : "=l"(lo)
                        : "f"(wf.x), "f"(wf.y));
                    asm("mov.b64 %0, {%1, %2};" : "=l"(hi)
                        : "f"(wf.z), "f"(wf.w));
                    w2[2 * j]     = lo;
                    w2[2 * j + 1] = hi;
                }
#pragma unroll
                for (int p = 0; p < PXC; p++) {
                    const unsigned long long xv = pk[p + kx];
#pragma unroll
                    for (int op = 0; op < NOP; op++)
                        FMA2(acc[op][p], w2[op], xv);
                }
            }
        }
    };

    loadch(0, rawA);

#pragma unroll 1
    for (int ic = 0; ic < IC; ic += 2) {
        loadch(ic + 1, rawB);                           // prefetch odd channel
        compute(ic, rawA);
        loadch((ic + 2 < IC) ? ic + 2 : IC - 1, rawA);  // prefetch next even
        compute(ic + 1, rawB);
    }

    const float inv = rsqrtf(1.f + 1e-5f);
#pragma unroll
    for (int op = 0; op < NOP; op++) {
        const int oc = g * OCPT + 2 * op;
        const float s0 = gamma[oc] * inv,  s1 = gamma[oc + 1] * inv;
        const float c0 = beta[oc],         c1 = beta[oc + 1];
        float* o0 = out + (size_t)(b * OC + oc) * planeO
                        + (size_t)(oy + 1) * PWO + 1;
        float* o1 = o0 + planeO;
#pragma unroll
        for (int p = 0; p < PXC; p++) {
            if (x0 + p < OW) {
                float2 a;
                memcpy(&a, &acc[op][p], 8);
                o0[x0 + p] = fmaxf(fmaf(a.x, s0, c0), 0.f);
                o1[x0 + p] = fmaxf(fmaf(a.y, s1, c1), 0.f);
            }
        }
    }
}

// ---------------------------------------------------------------------------
// conv1 fused with padding: reads the RAW image (bounds-checked, zero-fill),
// writes into padded x1. IC=3, OC=32, stride 2.
// ---------------------------------------------------------------------------
template<int OCPT, int PXC>
__global__ void __launch_bounds__(128, 4)
conv1_raw(const float* __restrict__ img,
          const float* __restrict__ wgt, const float* __restrict__ gamma,
          const float* __restrict__ beta, float* __restrict__ out)
{
    constexpr int IC  = 3;
    constexpr int OC  = 32;
    constexpr int NG  = OC / OCPT;
    constexpr int NOP = OCPT / 2;
    constexpr int NF4 = NOP / 2;
    constexpr int NIN = (PXC - 1) * 2 + 3;
    constexpr int OW  = 704;

    int z = blockIdx.z;
    const int g = z % NG;
    const int b = z / NG;

    const int l  = threadIdx.x;
    const int oy = blockIdx.y * 4 + threadIdx.y;
    const int x0 = (blockIdx.x * 32 + l) * PXC;

    __shared__ __align__(16) float ws[IC * 9 * OCPT];
    {
        const int tid = threadIdx.y * 32 + l;
        const float* wsrc = wgt + (size_t)(g * OCPT) * IC * 9;
        for (int i = tid; i < IC * 9 * OCPT; i += 128) {
            const int ocl = i % OCPT;
            const int t   = (i / OCPT) % 9;
            const int ic  = i / (OCPT * 9);
            ws[i] = wsrc[((size_t)ocl * IC + ic) * 9 + t];
        }
    }
    __syncthreads();

    unsigned long long acc[NOP][PXC];
#pragma unroll
    for (int op = 0; op < NOP; op++)
#pragma unroll
        for (int p = 0; p < PXC; p++) acc[op][p] = 0ULL;

#pragma unroll
    for (int ic = 0; ic < IC; ic++) {
        const float* plane = img + (size_t)(b * IC + ic) * IMG_H * IMG_W;
#pragma unroll
        for (int ky = 0; ky < 3; ky++) {
            const int iy = oy * 2 - 1 + ky;
            const bool yok = (iy >= 0) & (iy < IMG_H);
            const float* row = plane + (size_t)iy * IMG_W;

            unsigned long long pk[NIN];
#pragma unroll
            for (int c = 0; c < NIN; c++) {
                const int ix = x0 * 2 - 1 + c;
                const float v = (yok && ix >= 0 && ix < IMG_W) ? row[ix] : 0.f;
                pk[c] = pack2(v);
            }
#pragma unroll
            for (int kx = 0; kx < 3; kx++) {
                const float* wr = ws + (ic * 9 + ky * 3 + kx) * OCPT;
                unsigned long long w2[NOP];
#pragma unroll
                for (int j = 0; j < NF4; j++) {
                    const float4 wf = *(const float4*)(wr + 4 * j);
                    unsigned long long lo, hi;
                    asm("mov.b64 %0, {%1, %2};" : "=l"(lo)
                        : "f"(wf.x), "f"(wf.y));
                    asm("mov.b64 %0, {%1, %2};" : "=l"(hi)
                        : "f"(wf.z), "f"(wf.w));
                    w2[2 * j]     = lo;
                    w2[2 * j + 1] = hi;
                }
#pragma unroll
                for (int p = 0; p < PXC; p++) {
                    const unsigned long long xv = pk[p * 2 + kx];
#pragma unroll
                    for (int op = 0; op < NOP; op++)
                        FMA2(acc[op][p], w2[op], xv);
                }
            }
        }
    }

    const float inv = rsqrtf(1.f + 1e-5f);
#pragma unroll
    for (int op = 0; op < NOP; op++) {
        const int oc = g * OCPT + 2 * op;
        const float s0 = gamma[oc] * inv,  s1 = gamma[oc + 1] * inv;
        const float c0 = beta[oc],         c1 = beta[oc + 1];
        float* o0 = out + (size_t)(b * OC + oc) * PLANE1
                        + (size_t)(oy + 1) * PW1 + 1;
        float* o1 = o0 + PLANE1;
#pragma unroll
        for (int p = 0; p < PXC; p++) {
            if (x0 + p < OW) {
                float2 a;
                memcpy(&a, &acc[op][p], 8);
                o0[x0 + p] = fmaxf(fmaf(a.x, s0, c0), 0.f);
                o1[x0 + p] = fmaxf(fmaf(a.y, s1, c1), 0.f);
            }
        }
    }
}

// ---------------------------------------------------------------------------
// 1x1 conv (96 -> 1) + bias (reads padded feature maps).
// ---------------------------------------------------------------------------
template<int MODE>
__global__ void head1x1(const float* __restrict__ feat,
                        const float* __restrict__ w,
                        const float* __restrict__ bias,
                        float* __restrict__ out)
{
    const int idx = blockIdx.x * blockDim.x + threadIdx.x;
    if (idx >= BATCH * NPIX) return;
    const int b = idx / NPIX;
    const int p = idx % NPIX;
    const int y = p / FW;
    const int x = p % FW;
    float s = bias[0];
    const float* fb = feat + (size_t)b * 96 * PLANE3
                           + (size_t)(y + 1) * PW3 + (x + 1);
#pragma unroll 8
    for (int ic = 0; ic < 96; ic++)
        s += fb[(size_t)ic * PLANE3] * w[ic];
    if (MODE == 0) {
        out[idx] = s;
    } else {
        const float sig = 1.f / (1.f + expf(-s));
        out[idx] = 1.0f + sig * 79.0f;
    }
}

// ---------------------------------------------------------------------------
// Zero the BEV accumulation region
// ---------------------------------------------------------------------------
__global__ void zero_bev(float* __restrict__ bev)
{
    const int i = blockIdx.x * blockDim.x + threadIdx.x;
    if (i < BEV_SZ) bev[i] = 0.f;
}

// ---------------------------------------------------------------------------
// Projection + 5x5 Gaussian max-splat for one detection
// ---------------------------------------------------------------------------
__device__ __forceinline__ void splat_one(int b, int idx, float score,
                                          const float* __restrict__ depth,
                                          const float* __restrict__ P,
                                          const float* __restrict__ T,
                                          float* __restrict__ bev)
{
    if (score < THR) return;
    const int ys = idx / FW;
    const int xs = idx % FW;
    const float d = depth[b * NPIX + idx];
    const float u = (xs + 0.5f) * ((float)IMG_W / (float)FW);
    const float v = (ys + 0.5f) * ((float)IMG_H / (float)FH);

    const float* Pb = P + b * 12;
    const float fx = fmaxf(Pb[0], EPSV);
    const float fy = fmaxf(Pb[5], EPSV);
    const float cx = Pb[2], cy = Pb[6];
    const float tx = Pb[3], ty = Pb[7];
    const float xc = (u * d - cx * d - tx) / fx;
    const float yc = (v * d - cy * d - ty) / fy;

    const float* Tb = T + b * 16;
    const float lx = Tb[0]*xc + Tb[1]*yc + Tb[2]*d + Tb[3];
    const float ly = Tb[4]*xc + Tb[5]*yc + Tb[6]*d + Tb[7];

    const int gx = (int)floorf((lx + 51.2f) / 0.2f);
    const int gy = (int)floorf((ly + 51.2f) / 0.2f);

    if (gx < 0 || gx >= BEV || gy < 0 || gy >= BEV) return;

    const float isig = 18.f / 25.f;
    float* bb = bev + (size_t)b * BEV * BEV;
#pragma unroll
    for (int dy = -2; dy <= 2; dy++) {
        const int iy = gy + dy;
        if (iy < 0 || iy >= BEV) continue;
#pragma unroll
        for (int dx = -2; dx <= 2; dx++) {
            const int ix = gx + dx;
            if (ix < 0 || ix >= BEV) continue;
            const float val = score * expf(-(float)(dy*dy + dx*dx) * isig);
            atomicMax((int*)&bb[iy * BEV + ix], __float_as_int(val));
        }
    }
}

// ---------------------------------------------------------------------------
// Per-batch top-200 via 4-pass radix select + parallel splat.
// ---------------------------------------------------------------------------
#define EQCAP 256
__global__ void __launch_bounds__(1024, 1)
topk_splat(const float* __restrict__ hm,
           const float* __restrict__ depth,
           const float* __restrict__ P,
           const float* __restrict__ T,
           float* __restrict__ bev)
{
    const int b   = blockIdx.x;
    const int tid = threadIdx.x;

    __shared__ float prob[NPIX];
    __shared__ unsigned cnt[256];
    __shared__ int eq[EQCAP];
    __shared__ int eq_n;
    __shared__ unsigned s_prefix;
    __shared__ int s_need;

    for (int i = tid; i < NPIX; i += 1024) {
        const float x = hm[b * NPIX + i];
        prob[i] = 1.f / (1.f + expf(-x));
    }
    if (tid == 0) { s_prefix = 0u; s_need = TOPK; eq_n = 0; }
    __syncthreads();

    for (int pass = 0; pass < 4; pass++) {
        const int shift = 24 - 8 * pass;
        const unsigned pm = (pass == 0) ? 0u : (0xFFFFFFFFu << (32 - 8 * pass));
        if (tid < 256) cnt[tid] = 0;
        __syncthreads();
        const unsigned pref = s_prefix;
        for (int i = tid; i < NPIX; i += 1024) {
            const unsigned u = __float_as_uint(prob[i]);
            if ((u & pm) == pref)
                atomicAdd(&cnt[(u >> shift) & 255u], 1u);
        }
        __syncthreads();
        if (tid == 0) {
            int c = 0;
            const int nb = s_need;
            for (int bb = 255; bb >= 0; bb--) {
                const int cb = (int)cnt[bb];
                if (c + cb >= nb) {
                    s_prefix |= (unsigned)bb << shift;
                    s_need = nb - c;
                    break;
                }
                c += cb;
            }
        }
        __syncthreads();
    }

    const unsigned v200 = s_prefix;

    for (int i = tid; i < NPIX; i += 1024) {
        const unsigned u = __float_as_uint(prob[i]);
        if (u > v200) {
            splat_one(b, i, prob[i], depth, P, T, bev);
        } else if (u == v200) {
            const int p = atomicAdd(&eq_n, 1);
            if (p < EQCAP) eq[p] = i;
        }
    }
    __syncthreads();

    if (tid == 0) {
        const int n = (eq_n < EQCAP) ? eq_n : EQCAP;
        const int need = (s_need < n) ? s_need : n;
        for (int k = 0; k < need; k++) {
            int mi = k;
            for (int j = k + 1; j < n; j++)
                if (eq[j] < eq[mi]) mi = j;
            const int t = eq[k]; eq[k] = eq[mi]; eq[mi] = t;
        }
    }
    __syncthreads();

    if (tid < s_need && tid < EQCAP && tid < eq_n) {
        const int i = eq[tid];
        splat_one(b, i, prob[i], depth, P, T, bev);
    }
}

// ---------------------------------------------------------------------------
// Finalize: clip to prob, compute logits. Fast path for untouched cells.
// ---------------------------------------------------------------------------
__global__ void finalize_bev(float* __restrict__ out)
{
    const int i = blockIdx.x * blockDim.x + threadIdx.x;
    if (i >= BEV_SZ) return;
    float p = out[OFF_PROB + i];
    if (p <= EPSV) {
        out[OFF_PROB + i]   = EPSV;
        out[OFF_LOGITS + i] = -9.2102404f;
    } else {
        p = fminf(p, 1.f - EPSV);
        out[OFF_PROB + i]   = p;
        out[OFF_LOGITS + i] = logf(p) - log1pf(-p);
    }
}

// ---------------------------------------------------------------------------
// Launcher
// ---------------------------------------------------------------------------
extern "C" void kernel_launch(void* const* d_in, const int* in_sizes, int n_in,
                              void* d_out, int out_size)
{
    (void)in_sizes; (void)n_in; (void)out_size;

    const float* image = (const float*)d_in[0];
    const float* P     = (const float*)d_in[1];
    const float* T     = (const float*)d_in[2];
    const float* W1  = (const float*)d_in[3];
    const float* g1  = (const float*)d_in[4];
    const float* b1  = (const float*)d_in[5];
    const float* W2  = (const float*)d_in[6];
    const float* g2  = (const float*)d_in[7];
    const float* b2  = (const float*)d_in[8];
    const float* W3  = (const float*)d_in[9];
    const float* g3  = (const float*)d_in[10];
    const float* b3  = (const float*)d_in[11];
    const float* Wh1 = (const float*)d_in[12];
    const float* gh1 = (const float*)d_in[13];
    const float* bh1 = (const float*)d_in[14];
    const float* Wh2 = (const float*)d_in[15];
    const float* bh2 = (const float*)d_in[16];
    const float* Wd1 = (const float*)d_in[17];
    const float* gd1 = (const float*)d_in[18];
    const float* bd1 = (const float*)d_in[19];
    const float* Wd2 = (const float*)d_in[20];
    const float* bd2 = (const float*)d_in[21];

    float* out = (float*)d_out;

    float *x1, *x2, *feats, *h1, *d1;
    cudaGetSymbolAddress((void**)&x1,    g_x1);
    cudaGetSymbolAddress((void**)&x2,    g_x2);
    cudaGetSymbolAddress((void**)&feats, g_feats);
    cudaGetSymbolAddress((void**)&h1,    g_h1);
    cudaGetSymbolAddress((void**)&d1,    g_d1);

    dim3 blk(32, 4);

    // conv1 (pad fused): 3 -> 32, stride 2, OCPT=16, PXC=4
    conv1_raw<16, 4><<<dim3(6, 64, BATCH * 2), blk>>>(image, W1, g1, b1, x1);

    // conv2: 32 -> 64, stride 2, OCPT=16, PXC=4
    convp<32, 64, 16, 2, 4, 0><<<dim3(3, 32, BATCH * 4), blk>>>(
        x1, PW1, PLANE1, 128, 352, PW2, PLANE2,
        W2, g2, b2, x2, nullptr, nullptr, nullptr, nullptr);

    // conv3: 64 -> 96, stride 2, OCPT=12, PXC=6
    convp<64, 96, 12, 2, 6, 0><<<dim3(1, 16, BATCH * 8), blk>>>(
        x2, PW2, PLANE2, 64, 176, PW3, PLANE3,
        W3, g3, b3, feats, nullptr, nullptr, nullptr, nullptr);

    // both head hidden convs (fused, channel-prefetch pipelined):
    // 96 -> 96, stride 1, OCPT=12, PXC=6
    convpf<96, 96, 12, 6, 1><<<dim3(1, 16, BATCH * 2 * 8), blk>>>(
        feats, PW3, PLANE3, 64, 176, PW3, PLANE3,
        Wh1, gh1, bh1, h1, Wd1, gd1, bd1, d1);

    // 1x1 heads
    head1x1<0><<<(BATCH * NPIX + 255) / 256, 256>>>(h1, Wh2, bh2, out + OFF_HM);
    head1x1<1><<<(BATCH * NPIX + 255) / 256, 256>>>(d1, Wd2, bd2, out + OFF_DEPTH);

    // BEV accumulate (prob region), radix-select + splat, finalize
    zero_bev<<<(BEV_SZ + 255) / 256, 256>>>(out + OFF_PROB);
    topk_splat<<<BATCH, 1024>>>(out + OFF_HM, out + OFF_DEPTH, P, T, out + OFF_PROB);
    finalize_bev<<<(BEV_SZ + 255) / 256, 256>>>(out);
}

// round 17
// speedup vs baseline: 1.1191x; 1.0477x over previous
#include <cuda_runtime.h>
#include <cuda_bf16.h>
#include <math.h>
#include <string.h>

// ---------------------------------------------------------------------------
// Problem constants
// ---------------------------------------------------------------------------
#define BATCH 4
#define IMG_H 512
#define IMG_W 1408
#define FH 64
#define FW 176
#define NPIX (FH*FW)            // 11264
#define HM_SZ (BATCH*NPIX)      // 45056
#define BEV 512
#define BEV_SZ (BATCH*BEV*BEV)  // 1048576
#define TOPK 200
#define THR 0.15f
#define EPSV 1e-4f

#define OFF_HM     0
#define OFF_DEPTH  (HM_SZ)
#define OFF_LOGITS (2*HM_SZ)
#define OFF_PROB   (2*HM_SZ + BEV_SZ)

// Padded geometry (1-px halo, width padded to mult of 4)
#define PW1 708
#define PH1 258
#define PLANE1 (PH1*PW1)        // x1: 32 ch, 256x704
#define PW2 356
#define PH2 130
#define PLANE2 (PH2*PW2)        // x2: 64 ch, 128x352
#define PW3 180
#define PH3 66
#define PLANE3 (PH3*PW3)        // feats: 96 ch, 64x176

#define HEAD_NG 8               // 96 / OCPT(12) groups in head conv

// ---------------------------------------------------------------------------
// Scratch (device globals: zero-initialized at module load; halos never
// written by any kernel, so they remain zero across all graph replays)
// ---------------------------------------------------------------------------
__device__ float g_x1[BATCH*32*PLANE1 + 4096];
__device__ float g_x2[BATCH*64*PLANE2 + 4096];
__device__ float g_feats[BATCH*96*PLANE3 + 4096];
__device__ float g_part[2*BATCH*HEAD_NG*NPIX + 4096];   // 1x1 partial sums

// ---------------------------------------------------------------------------
// f32x2 packed math helpers
// ---------------------------------------------------------------------------
__device__ __forceinline__ unsigned long long pack2(float x) {
    unsigned long long r;
    const unsigned int u = __float_as_uint(x);
    asm("mov.b64 %0, {%1, %1};" : "=l"(r) : "r"(u));
    return r;
}
#define FMA2(acc, a, b) \
    asm("fma.rn.f32x2 %0, %1, %2, %0;" : "+l"(acc) : "l"(a), "l"(b))

// ---------------------------------------------------------------------------
// Padded direct 3x3 conv + BN(eval) + ReLU using packed f32x2 FMAs (R7 core).
// Used for conv2 and conv3.
// ---------------------------------------------------------------------------
template<int IC, int OC, int OCPT, int STRIDE, int PXC>
__global__ void __launch_bounds__(128, 4)
convp(const float* __restrict__ in, int PWI, int planeI,
      int OH, int OW, int PWO, int planeO,
      const float* __restrict__ wgt, const float* __restrict__ gamma,
      const float* __restrict__ beta, float* __restrict__ out)
{
    constexpr int NG  = OC / OCPT;
    constexpr int NOP = OCPT / 2;
    constexpr int NF4 = NOP / 2;
    constexpr int NIN = (PXC - 1) * STRIDE + 3;
    constexpr int NV2 = (NIN + 1) / 2;

    int z = blockIdx.z;
    const int g = z % NG;
    const int b = z / NG;

    const int l  = threadIdx.x;
    const int oy = blockIdx.y * 4 + threadIdx.y;
    const int x0 = (blockIdx.x * 32 + l) * PXC;

    __shared__ __align__(16) float ws[IC * 9 * OCPT];
    {
        const int tid = threadIdx.y * 32 + l;
        const float* wsrc = wgt + (size_t)(g * OCPT) * IC * 9;
        for (int i = tid; i < IC * 9 * OCPT; i += 128) {
            const int ocl = i % OCPT;
            const int t   = (i / OCPT) % 9;
            const int ic  = i / (OCPT * 9);
            ws[i] = wsrc[((size_t)ocl * IC + ic) * 9 + t];
        }
    }
    __syncthreads();

    unsigned long long acc[NOP][PXC];
#pragma unroll
    for (int op = 0; op < NOP; op++)
#pragma unroll
        for (int p = 0; p < PXC; p++) acc[op][p] = 0ULL;

    const float* inb = in + (size_t)b * IC * planeI;

#pragma unroll 1
    for (int ic = 0; ic < IC; ic++) {
        const float* plane = inb + (size_t)ic * planeI;
#pragma unroll
        for (int ky = 0; ky < 3; ky++) {
            const float* rp = plane + (size_t)(oy * STRIDE + ky) * PWI
                                    + (size_t)x0 * STRIDE;
            unsigned long long pk[NIN];
            {
                float v[NV2 * 2];
#pragma unroll
                for (int i = 0; i < NV2; i++) {
                    const float2 t2 = *(const float2*)(rp + 2 * i);
                    v[2 * i]     = t2.x;
                    v[2 * i + 1] = t2.y;
                }
#pragma unroll
                for (int c = 0; c < NIN; c++) pk[c] = pack2(v[c]);
            }
#pragma unroll
            for (int kx = 0; kx < 3; kx++) {
                const float* wr = ws + (ic * 9 + ky * 3 + kx) * OCPT;
                unsigned long long w2[NOP];
#pragma unroll
                for (int j = 0; j < NF4; j++) {
                    const float4 wf = *(const float4*)(wr + 4 * j);
                    unsigned long long lo, hi;
                    asm("mov.b64 %0, {%1, %2};" : "=l"(lo)
                        : "f"(wf.x), "f"(wf.y));
                    asm("mov.b64 %0, {%1, %2};" : "=l"(hi)
                        : "f"(wf.z), "f"(wf.w));
                    w2[2 * j]     = lo;
                    w2[2 * j + 1] = hi;
                }
#pragma unroll
                for (int p = 0; p < PXC; p++) {
                    const unsigned long long xv = pk[p * STRIDE + kx];
#pragma unroll
                    for (int op = 0; op < NOP; op++)
                        FMA2(acc[op][p], w2[op], xv);
                }
            }
        }
    }

    const float inv = rsqrtf(1.f + 1e-5f);
#pragma unroll
    for (int op = 0; op < NOP; op++) {
        const int oc = g * OCPT + 2 * op;
        const float s0 = gamma[oc] * inv,  s1 = gamma[oc + 1] * inv;
        const float c0 = beta[oc],         c1 = beta[oc + 1];
        float* o0 = out + (size_t)(b * OC + oc) * planeO
                        + (size_t)(oy + 1) * PWO + 1;
        float* o1 = o0 + planeO;
#pragma unroll
        for (int p = 0; p < PXC; p++) {
            if (x0 + p < OW) {
                float2 a;
                memcpy(&a, &acc[op][p], 8);
                o0[x0 + p] = fmaxf(fmaf(a.x, s0, c0), 0.f);
                o1[x0 + p] = fmaxf(fmaf(a.y, s1, c1), 0.f);
            }
        }
    }
}

// ---------------------------------------------------------------------------
// HEAD conv, stride 1, channel-prefetch ping-pong, with FUSED 1x1 partial
// sums: instead of storing the 12-channel hidden tile, the epilogue applies
// BN+ReLU, multiplies by the 1x1 head weights and writes ONE partial float
// per pixel to the compact partials buffer part[(head*BATCH+b)*NG+g][pix].
// Deterministic: fixed per-pixel summation order over the 12 channels.
// ---------------------------------------------------------------------------
template<int IC, int OC, int OCPT, int PXC>
__global__ void __launch_bounds__(128, 3)
convhf(const float* __restrict__ in, int PWI, int planeI,
       const float* __restrict__ w0, const float* __restrict__ ga0,
       const float* __restrict__ be0, const float* __restrict__ v0,
       const float* __restrict__ w1, const float* __restrict__ ga1,
       const float* __restrict__ be1, const float* __restrict__ v1,
       float* __restrict__ part)
{
    constexpr int NG  = OC / OCPT;
    constexpr int NOP = OCPT / 2;
    constexpr int NF4 = NOP / 2;
    constexpr int NIN = PXC + 2;
    constexpr int NV2 = (NIN + 1) / 2;

    int z = blockIdx.z;
    const int g = z % NG;  z /= NG;
    const int head = z & 1;  z >>= 1;
    const int b = z;

    const float* wgt   = head ? w1 : w0;
    const float* gamma = head ? ga1 : ga0;
    const float* beta  = head ? be1 : be0;
    const float* v1x1  = head ? v1 : v0;

    const int l  = threadIdx.x;
    const int oy = blockIdx.y * 4 + threadIdx.y;
    const int x0 = (blockIdx.x * 32 + l) * PXC;

    __shared__ __align__(16) float ws[IC * 9 * OCPT];
    {
        const int tid = threadIdx.y * 32 + l;
        const float* wsrc = wgt + (size_t)(g * OCPT) * IC * 9;
        for (int i = tid; i < IC * 9 * OCPT; i += 128) {
            const int ocl = i % OCPT;
            const int t   = (i / OCPT) % 9;
            const int ic  = i / (OCPT * 9);
            ws[i] = wsrc[((size_t)ocl * IC + ic) * 9 + t];
        }
    }
    __syncthreads();

    unsigned long long acc[NOP][PXC];
#pragma unroll
    for (int op = 0; op < NOP; op++)
#pragma unroll
        for (int p = 0; p < PXC; p++) acc[op][p] = 0ULL;

    const float* inb = in + (size_t)b * IC * planeI;
    const size_t rowbase = (size_t)oy * PWI + (size_t)x0;

    float rawA[3][NV2 * 2], rawB[3][NV2 * 2];

    auto loadch = [&](int ic_, float (*raw)[NV2 * 2]) {
        const float* plane = inb + (size_t)ic_ * planeI + rowbase;
#pragma unroll
        for (int ky = 0; ky < 3; ky++) {
            const float* rp = plane + (size_t)ky * PWI;
#pragma unroll
            for (int i = 0; i < NV2; i++) {
                const float2 t2 = *(const float2*)(rp + 2 * i);
                raw[ky][2 * i]     = t2.x;
                raw[ky][2 * i + 1] = t2.y;
            }
        }
    };

    auto compute = [&](int ic_, float (*raw)[NV2 * 2]) {
        const float* wc = ws + ic_ * 9 * OCPT;
#pragma unroll
        for (int ky = 0; ky < 3; ky++) {
            unsigned long long pk[NIN];
#pragma unroll
            for (int c = 0; c < NIN; c++) pk[c] = pack2(raw[ky][c]);
#pragma unroll
            for (int kx = 0; kx < 3; kx++) {
                const float* wr = wc + (ky * 3 + kx) * OCPT;
                unsigned long long w2[NOP];
#pragma unroll
                for (int j = 0; j < NF4; j++) {
                    const float4 wf = *(const float4*)(wr + 4 * j);
                    unsigned long long lo, hi;
                    asm("mov.b64 %0, {%1, %2};" : "=l"(lo)
                        : "f"(wf.x), "f"(wf.y));
                    asm("mov.b64 %0, {%1, %2};" : "=l"(hi)
                        : "f"(wf.z), "f"(wf.w));
                    w2[2 * j]     = lo;
                    w2[2 * j + 1] = hi;
                }
#pragma unroll
                for (int p = 0; p < PXC; p++) {
                    const unsigned long long xv = pk[p + kx];
#pragma unroll
                    for (int op = 0; op < NOP; op++)
                        FMA2(acc[op][p], w2[op], xv);
                }
            }
        }
    };

    loadch(0, rawA);

#pragma unroll 1
    for (int ic = 0; ic < IC; ic += 2) {
        loadch(ic + 1, rawB);                           // prefetch odd channel
        compute(ic, rawA);
        loadch((ic + 2 < IC) ? ic + 2 : IC - 1, rawA);  // prefetch next even
        compute(ic + 1, rawB);
    }

    // epilogue: BN + ReLU + 1x1 partial sum per pixel (fixed channel order)
    const float inv = rsqrtf(1.f + 1e-5f);
    float psum[PXC];
#pragma unroll
    for (int p = 0; p < PXC; p++) psum[p] = 0.f;

#pragma unroll
    for (int op = 0; op < NOP; op++) {
        const int oc = g * OCPT + 2 * op;
        const float s0 = gamma[oc] * inv,  s1 = gamma[oc + 1] * inv;
        const float c0 = beta[oc],         c1 = beta[oc + 1];
        const float u0 = v1x1[oc],         u1 = v1x1[oc + 1];
#pragma unroll
        for (int p = 0; p < PXC; p++) {
            float2 a;
            memcpy(&a, &acc[op][p], 8);
            const float r0 = fmaxf(fmaf(a.x, s0, c0), 0.f);
            const float r1 = fmaxf(fmaf(a.y, s1, c1), 0.f);
            psum[p] = fmaf(r0, u0, psum[p]);
            psum[p] = fmaf(r1, u1, psum[p]);
        }
    }

    float* prow = part + ((size_t)((head * BATCH + b) * NG + g)) * NPIX
                       + (size_t)oy * FW;
#pragma unroll
    for (int p = 0; p < PXC; p++)
        if (x0 + p < FW) prow[x0 + p] = psum[p];
}

// ---------------------------------------------------------------------------
// conv1 fused with padding: reads the RAW image (bounds-checked, zero-fill),
// writes into padded x1. IC=3, OC=32, stride 2.
// ---------------------------------------------------------------------------
template<int OCPT, int PXC>
__global__ void __launch_bounds__(128, 4)
conv1_raw(const float* __restrict__ img,
          const float* __restrict__ wgt, const float* __restrict__ gamma,
          const float* __restrict__ beta, float* __restrict__ out)
{
    constexpr int IC  = 3;
    constexpr int OC  = 32;
    constexpr int NG  = OC / OCPT;
    constexpr int NOP = OCPT / 2;
    constexpr int NF4 = NOP / 2;
    constexpr int NIN = (PXC - 1) * 2 + 3;
    constexpr int OW  = 704;

    int z = blockIdx.z;
    const int g = z % NG;
    const int b = z / NG;

    const int l  = threadIdx.x;
    const int oy = blockIdx.y * 4 + threadIdx.y;
    const int x0 = (blockIdx.x * 32 + l) * PXC;

    __shared__ __align__(16) float ws[IC * 9 * OCPT];
    {
        const int tid = threadIdx.y * 32 + l;
        const float* wsrc = wgt + (size_t)(g * OCPT) * IC * 9;
        for (int i = tid; i < IC * 9 * OCPT; i += 128) {
            const int ocl = i % OCPT;
            const int t   = (i / OCPT) % 9;
            const int ic  = i / (OCPT * 9);
            ws[i] = wsrc[((size_t)ocl * IC + ic) * 9 + t];
        }
    }
    __syncthreads();

    unsigned long long acc[NOP][PXC];
#pragma unroll
    for (int op = 0; op < NOP; op++)
#pragma unroll
        for (int p = 0; p < PXC; p++) acc[op][p] = 0ULL;

#pragma unroll
    for (int ic = 0; ic < IC; ic++) {
        const float* plane = img + (size_t)(b * IC + ic) * IMG_H * IMG_W;
#pragma unroll
        for (int ky = 0; ky < 3; ky++) {
            const int iy = oy * 2 - 1 + ky;
            const bool yok = (iy >= 0) & (iy < IMG_H);
            const float* row = plane + (size_t)iy * IMG_W;

            unsigned long long pk[NIN];
#pragma unroll
            for (int c = 0; c < NIN; c++) {
                const int ix = x0 * 2 - 1 + c;
                const float v = (yok && ix >= 0 && ix < IMG_W) ? row[ix] : 0.f;
                pk[c] = pack2(v);
            }
#pragma unroll
            for (int kx = 0; kx < 3; kx++) {
                const float* wr = ws + (ic * 9 + ky * 3 + kx) * OCPT;
                unsigned long long w2[NOP];
#pragma unroll
                for (int j = 0; j < NF4; j++) {
                    const float4 wf = *(const float4*)(wr + 4 * j);
                    unsigned long long lo, hi;
                    asm("mov.b64 %0, {%1, %2};" : "=l"(lo)
                        : "f"(wf.x), "f"(wf.y));
                    asm("mov.b64 %0, {%1, %2};" : "=l"(hi)
                        : "f"(wf.z), "f"(wf.w));
                    w2[2 * j]     = lo;
                    w2[2 * j + 1] = hi;
                }
#pragma unroll
                for (int p = 0; p < PXC; p++) {
                    const unsigned long long xv = pk[p * 2 + kx];
#pragma unroll
                    for (int op = 0; op < NOP; op++)
                        FMA2(acc[op][p], w2[op], xv);
                }
            }
        }
    }

    const float inv = rsqrtf(1.f + 1e-5f);
#pragma unroll
    for (int op = 0; op < NOP; op++) {
        const int oc = g * OCPT + 2 * op;
        const float s0 = gamma[oc] * inv,  s1 = gamma[oc + 1] * inv;
        const float c0 = beta[oc],         c1 = beta[oc + 1];
        float* o0 = out + (size_t)(b * OC + oc) * PLANE1
                        + (size_t)(oy + 1) * PW1 + 1;
        float* o1 = o0 + PLANE1;
#pragma unroll
        for (int p = 0; p < PXC; p++) {
            if (x0 + p < OW) {
                float2 a;
                memcpy(&a, &acc[op][p], 8);
                o0[x0 + p] = fmaxf(fmaf(a.x, s0, c0), 0.f);
                o1[x0 + p] = fmaxf(fmaf(a.y, s1, c1), 0.f);
            }
        }
    }
}

// ---------------------------------------------------------------------------
// 1x1 head finalize: reduce HEAD_NG group partials + bias.
// mode 0: raw logits (hm). mode 1: depth transform.
// ---------------------------------------------------------------------------
template<int MODE>
__global__ void head_reduce(const float* __restrict__ part,
                            const float* __restrict__ bias,
                            float* __restrict__ out)
{
    const int idx = blockIdx.x * blockDim.x + threadIdx.x;
    if (idx >= BATCH * NPIX) return;
    const int b = idx / NPIX;
    const int p = idx % NPIX;
    const float* pb = part + ((size_t)((MODE * BATCH + b) * HEAD_NG)) * NPIX + p;
    float s = bias[0];
#pragma unroll
    for (int g = 0; g < HEAD_NG; g++)
        s += pb[(size_t)g * NPIX];
    if (MODE == 0) {
        out[idx] = s;
    } else {
        const float sig = 1.f / (1.f + expf(-s));
        out[idx] = 1.0f + sig * 79.0f;
    }
}

// ---------------------------------------------------------------------------
// Zero the BEV accumulation region
// ---------------------------------------------------------------------------
__global__ void zero_bev(float* __restrict__ bev)
{
    const int i = blockIdx.x * blockDim.x + threadIdx.x;
    if (i < BEV_SZ) bev[i] = 0.f;
}

// ---------------------------------------------------------------------------
// Projection + 5x5 Gaussian max-splat for one detection
// ---------------------------------------------------------------------------
__device__ __forceinline__ void splat_one(int b, int idx, float score,
                                          const float* __restrict__ depth,
                                          const float* __restrict__ P,
                                          const float* __restrict__ T,
                                          float* __restrict__ bev)
{
    if (score < THR) return;
    const int ys = idx / FW;
    const int xs = idx % FW;
    const float d = depth[b * NPIX + idx];
    const float u = (xs + 0.5f) * ((float)IMG_W / (float)FW);
    const float v = (ys + 0.5f) * ((float)IMG_H / (float)FH);

    const float* Pb = P + b * 12;
    const float fx = fmaxf(Pb[0], EPSV);
    const float fy = fmaxf(Pb[5], EPSV);
    const float cx = Pb[2], cy = Pb[6];
    const float tx = Pb[3], ty = Pb[7];
    const float xc = (u * d - cx * d - tx) / fx;
    const float yc = (v * d - cy * d - ty) / fy;

    const float* Tb = T + b * 16;
    const float lx = Tb[0]*xc + Tb[1]*yc + Tb[2]*d + Tb[3];
    const float ly = Tb[4]*xc + Tb[5]*yc + Tb[6]*d + Tb[7];

    const int gx = (int)floorf((lx + 51.2f) / 0.2f);
    const int gy = (int)floorf((ly + 51.2f) / 0.2f);

    if (gx < 0 || gx >= BEV || gy < 0 || gy >= BEV) return;

    const float isig = 18.f / 25.f;
    float* bb = bev + (size_t)b * BEV * BEV;
#pragma unroll
    for (int dy = -2; dy <= 2; dy++) {
        const int iy = gy + dy;
        if (iy < 0 || iy >= BEV) continue;
#pragma unroll
        for (int dx = -2; dx <= 2; dx++) {
            const int ix = gx + dx;
            if (ix < 0 || ix >= BEV) continue;
            const float val = score * expf(-(float)(dy*dy + dx*dx) * isig);
            atomicMax((int*)&bb[iy * BEV + ix], __float_as_int(val));
        }
    }
}

// ---------------------------------------------------------------------------
// Per-batch top-200 via 4-pass radix select + parallel splat.
// ---------------------------------------------------------------------------
#define EQCAP 256
__global__ void __launch_bounds__(1024, 1)
topk_splat(const float* __restrict__ hm,
           const float* __restrict__ depth,
           const float* __restrict__ P,
           const float* __restrict__ T,
           float* __restrict__ bev)
{
    const int b   = blockIdx.x;
    const int tid = threadIdx.x;

    __shared__ float prob[NPIX];
    __shared__ unsigned cnt[256];
    __shared__ int eq[EQCAP];
    __shared__ int eq_n;
    __shared__ unsigned s_prefix;
    __shared__ int s_need;

    for (int i = tid; i < NPIX; i += 1024) {
        const float x = hm[b * NPIX + i];
        prob[i] = 1.f / (1.f + expf(-x));
    }
    if (tid == 0) { s_prefix = 0u; s_need = TOPK; eq_n = 0; }
    __syncthreads();

    for (int pass = 0; pass < 4; pass++) {
        const int shift = 24 - 8 * pass;
        const unsigned pm = (pass == 0) ? 0u : (0xFFFFFFFFu << (32 - 8 * pass));
        if (tid < 256) cnt[tid] = 0;
        __syncthreads();
        const unsigned pref = s_prefix;
        for (int i = tid; i < NPIX; i += 1024) {
            const unsigned u = __float_as_uint(prob[i]);
            if ((u & pm) == pref)
                atomicAdd(&cnt[(u >> shift) & 255u], 1u);
        }
        __syncthreads();
        if (tid == 0) {
            int c = 0;
            const int nb = s_need;
            for (int bb = 255; bb >= 0; bb--) {
                const int cb = (int)cnt[bb];
                if (c + cb >= nb) {
                    s_prefix |= (unsigned)bb << shift;
                    s_need = nb - c;
                    break;
                }
                c += cb;
            }
        }
        __syncthreads();
    }

    const unsigned v200 = s_prefix;

    for (int i = tid; i < NPIX; i += 1024) {
        const unsigned u = __float_as_uint(prob[i]);
        if (u > v200) {
            splat_one(b, i, prob[i], depth, P, T, bev);
        } else if (u == v200) {
            const int p = atomicAdd(&eq_n, 1);
            if (p < EQCAP) eq[p] = i;
        }
    }
    __syncthreads();

    if (tid == 0) {
        const int n = (eq_n < EQCAP) ? eq_n : EQCAP;
        const int need = (s_need < n) ? s_need : n;
        for (int k = 0; k < need; k++) {
            int mi = k;
            for (int j = k + 1; j < n; j++)
                if (eq[j] < eq[mi]) mi = j;
            const int t = eq[k]; eq[k] = eq[mi]; eq[mi] = t;
        }
    }
    __syncthreads();

    if (tid < s_need && tid < EQCAP && tid < eq_n) {
        const int i = eq[tid];
        splat_one(b, i, prob[i], depth, P, T, bev);
    }
}

// ---------------------------------------------------------------------------
// Finalize: clip to prob, compute logits. Fast path for untouched cells.
// ---------------------------------------------------------------------------
__global__ void finalize_bev(float* __restrict__ out)
{
    const int i = blockIdx.x * blockDim.x + threadIdx.x;
    if (i >= BEV_SZ) return;
    float p = out[OFF_PROB + i];
    if (p <= EPSV) {
        out[OFF_PROB + i]   = EPSV;
        out[OFF_LOGITS + i] = -9.2102404f;
    } else {
        p = fminf(p, 1.f - EPSV);
        out[OFF_PROB + i]   = p;
        out[OFF_LOGITS + i] = logf(p) - log1pf(-p);
    }
}

// ---------------------------------------------------------------------------
// Launcher
// ---------------------------------------------------------------------------
extern "C" void kernel_launch(void* const* d_in, const int* in_sizes, int n_in,
                              void* d_out, int out_size)
{
    (void)in_sizes; (void)n_in; (void)out_size;

    const float* image = (const float*)d_in[0];
    const float* P     = (const float*)d_in[1];
    const float* T     = (const float*)d_in[2];
    const float* W1  = (const float*)d_in[3];
    const float* g1  = (const float*)d_in[4];
    const float* b1  = (const float*)d_in[5];
    const float* W2  = (const float*)d_in[6];
    const float* g2  = (const float*)d_in[7];
    const float* b2  = (const float*)d_in[8];
    const float* W3  = (const float*)d_in[9];
    const float* g3  = (const float*)d_in[10];
    const float* b3  = (const float*)d_in[11];
    const float* Wh1 = (const float*)d_in[12];
    const float* gh1 = (const float*)d_in[13];
    const float* bh1 = (const float*)d_in[14];
    const float* Wh2 = (const float*)d_in[15];
    const float* bh2 = (const float*)d_in[16];
    const float* Wd1 = (const float*)d_in[17];
    const float* gd1 = (const float*)d_in[18];
    const float* bd1 = (const float*)d_in[19];
    const float* Wd2 = (const float*)d_in[20];
    const float* bd2 = (const float*)d_in[21];

    float* out = (float*)d_out;

    float *x1, *x2, *feats, *part;
    cudaGetSymbolAddress((void**)&x1,    g_x1);
    cudaGetSymbolAddress((void**)&x2,    g_x2);
    cudaGetSymbolAddress((void**)&feats, g_feats);
    cudaGetSymbolAddress((void**)&part,  g_part);

    dim3 blk(32, 4);

    // conv1 (pad fused): 3 -> 32, stride 2, OCPT=16, PXC=4
    conv1_raw<16, 4><<<dim3(6, 64, BATCH * 2), blk>>>(image, W1, g1, b1, x1);

    // conv2: 32 -> 64, stride 2, OCPT=16, PXC=4
    convp<32, 64, 16, 2, 4><<<dim3(3, 32, BATCH * 4), blk>>>(
        x1, PW1, PLANE1, 128, 352, PW2, PLANE2, W2, g2, b2, x2);

    // conv3: 64 -> 96, stride 2, OCPT=12, PXC=6
    convp<64, 96, 12, 2, 6><<<dim3(1, 16, BATCH * 8), blk>>>(
        x2, PW2, PLANE2, 64, 176, PW3, PLANE3, W3, g3, b3, feats);

    // head hidden convs with fused 1x1 partial sums:
    // 96 -> 96, stride 1, OCPT=12, PXC=6, partials to g_part
    convhf<96, 96, 12, 6><<<dim3(1, 16, BATCH * 2 * 8), blk>>>(
        feats, PW3, PLANE3,
        Wh1, gh1, bh1, Wh2, Wd1, gd1, bd1, Wd2, part);

    // 1x1 head reductions (8 partials + bias each)
    head_reduce<0><<<(BATCH * NPIX + 255) / 256, 256>>>(part, bh2, out + OFF_HM);
    head_reduce<1><<<(BATCH * NPIX + 255) / 256, 256>>>(part, bd2, out + OFF_DEPTH);

    // BEV accumulate (prob region), radix-select + splat, finalize
    zero_bev<<<(BEV_SZ + 255) / 256, 256>>>(out + OFF_PROB);
    topk_splat<<<BATCH, 1024>>>(out + OFF_HM, out + OFF_DEPTH, P, T, out + OFF_PROB);
    finalize_bev<<<(BEV_SZ + 255) / 256, 256>>>(out);
}